// round 2
// baseline (speedup 1.0000x reference)
#include <cuda_runtime.h>

#define BATCH   2
#define LSEQ    2048
#define DMODEL  1024
#define NHEADS  16
#define DKH     64
#define BHN     (BATCH * NHEADS)     // 32
#define BLM     (BATCH * LSEQ)       // 4096
#define TOPK    (LSEQ / 2)           // 1024

// ---- scratch (static device arrays; allocation-free per harness rules) ----
__device__ float g_Q[(size_t)BLM * DMODEL];
__device__ float g_K[(size_t)BLM * DMODEL];
__device__ float g_V[(size_t)BLM * DMODEL];
__device__ float g_ctx[(size_t)BLM * DMODEL];
__device__ float g_S[(size_t)BHN * LSEQ * LSEQ];   // 537 MB scores/probs

// monotone float<->uint mapping (order-preserving)
__device__ __forceinline__ unsigned f2key(float f) {
    unsigned u = __float_as_uint(f);
    return (u & 0x80000000u) ? ~u : (u | 0x80000000u);
}
__device__ __forceinline__ float key2f(unsigned key) {
    unsigned u = (key & 0x80000000u) ? (key ^ 0x80000000u) : ~key;
    return __uint_as_float(u);
}

// ============================================================
// Generic GEMM: Y[m,n] = sum_k X[m,k]*W[n,k] + bias[n]
// X: [M, DMODEL] row-major, W: [DMODEL, DMODEL] row-major (used as W^T)
// Tile 64x64, BK=16, 256 threads, 4x4 per thread.
// ============================================================
__global__ __launch_bounds__(256) void gemm_xwT_bias(
    const float* __restrict__ X, const float* __restrict__ W,
    const float* __restrict__ bias, float* __restrict__ Y)
{
    __shared__ __align__(16) float Xs[16][64];
    __shared__ __align__(16) float Ws[16][64];
    const int tid = threadIdx.x;
    const int tx = tid & 15, ty = tid >> 4;
    const int m0 = blockIdx.y * 64, n0 = blockIdx.x * 64;
    const int lm  = tid >> 2;          // 0..63 tile row
    const int lc4 = (tid & 3) * 4;     // 0,4,8,12 col within BK

    float acc[4][4] = {};
    for (int k0 = 0; k0 < DMODEL; k0 += 16) {
        float4 xa = *(const float4*)(X + (size_t)(m0 + lm) * DMODEL + k0 + lc4);
        float4 wa = *(const float4*)(W + (size_t)(n0 + lm) * DMODEL + k0 + lc4);
        Xs[lc4 + 0][lm] = xa.x; Xs[lc4 + 1][lm] = xa.y;
        Xs[lc4 + 2][lm] = xa.z; Xs[lc4 + 3][lm] = xa.w;
        Ws[lc4 + 0][lm] = wa.x; Ws[lc4 + 1][lm] = wa.y;
        Ws[lc4 + 2][lm] = wa.z; Ws[lc4 + 3][lm] = wa.w;
        __syncthreads();
#pragma unroll
        for (int kk = 0; kk < 16; kk++) {
            float4 av = *(const float4*)&Xs[kk][ty * 4];
            float4 bv = *(const float4*)&Ws[kk][tx * 4];
            float a4[4] = {av.x, av.y, av.z, av.w};
            float b4[4] = {bv.x, bv.y, bv.z, bv.w};
#pragma unroll
            for (int i = 0; i < 4; i++)
#pragma unroll
                for (int j = 0; j < 4; j++)
                    acc[i][j] += a4[i] * b4[j];
        }
        __syncthreads();
    }
    float4 bb = *(const float4*)(bias + n0 + tx * 4);
#pragma unroll
    for (int i = 0; i < 4; i++) {
        float4 o;
        o.x = acc[i][0] + bb.x; o.y = acc[i][1] + bb.y;
        o.z = acc[i][2] + bb.z; o.w = acc[i][3] + bb.w;
        *(float4*)(Y + (size_t)(m0 + ty * 4 + i) * DMODEL + n0 + tx * 4) = o;
    }
}

// ============================================================
// Scores: S[bh][q][k] = (Q_bh[q,:] . K_bh[k,:]) / 8
// Q,K stored [b*L+l, h*64+d]. One block = 64x64 output tile, full d_k=64 in smem.
// ============================================================
__global__ __launch_bounds__(256) void scores_kernel()
{
    __shared__ __align__(16) float Qs[64][64];
    __shared__ __align__(16) float Ks[64][64];
    const int tid = threadIdx.x;
    const int tx = tid & 15, ty = tid >> 4;
    const int bh = blockIdx.z, b = bh >> 4, h = bh & 15;
    const int q0 = blockIdx.y * 64, k0 = blockIdx.x * 64;
    const float* Qb = g_Q + (size_t)b * LSEQ * DMODEL + h * DKH;
    const float* Kb = g_K + (size_t)b * LSEQ * DMODEL + h * DKH;

#pragma unroll
    for (int i = 0; i < 4; i++) {
        int f = tid + 256 * i;         // 0..1023
        int m  = f >> 4;               // row 0..63
        int c4 = (f & 15) * 4;         // col 0..60
        float4 qa = *(const float4*)(Qb + (size_t)(q0 + m) * DMODEL + c4);
        Qs[c4 + 0][m] = qa.x; Qs[c4 + 1][m] = qa.y;
        Qs[c4 + 2][m] = qa.z; Qs[c4 + 3][m] = qa.w;
        float4 ka = *(const float4*)(Kb + (size_t)(k0 + m) * DMODEL + c4);
        Ks[c4 + 0][m] = ka.x; Ks[c4 + 1][m] = ka.y;
        Ks[c4 + 2][m] = ka.z; Ks[c4 + 3][m] = ka.w;
    }
    __syncthreads();

    float acc[4][4] = {};
#pragma unroll 16
    for (int kk = 0; kk < 64; kk++) {
        float4 av = *(const float4*)&Qs[kk][ty * 4];
        float4 bv = *(const float4*)&Ks[kk][tx * 4];
        float a4[4] = {av.x, av.y, av.z, av.w};
        float b4[4] = {bv.x, bv.y, bv.z, bv.w};
#pragma unroll
        for (int i = 0; i < 4; i++)
#pragma unroll
            for (int j = 0; j < 4; j++)
                acc[i][j] += a4[i] * b4[j];
    }
    float* Sb = g_S + (size_t)bh * LSEQ * LSEQ;
#pragma unroll
    for (int i = 0; i < 4; i++) {
        float4 o;
        o.x = acc[i][0] * 0.125f; o.y = acc[i][1] * 0.125f;
        o.z = acc[i][2] * 0.125f; o.w = acc[i][3] * 0.125f;
        *(float4*)(Sb + (size_t)(q0 + ty * 4 + i) * LSEQ + k0 + tx * 4) = o;
    }
}

// ============================================================
// Per-row top-k threshold (radix select on monotone keys) + softmax,
// overwriting the score row with sparse probabilities (zeros outside top-k).
// One block (256 threads) per row.
// ============================================================
__global__ __launch_bounds__(256) void topk_softmax_kernel()
{
    __shared__ unsigned keys[LSEQ];
    __shared__ unsigned hist[256];
    __shared__ unsigned sA[256], sB[256];
    __shared__ float    fred[256];
    __shared__ unsigned s_sel, s_kkn, s_max, s_eq;
    __shared__ float    s_sum;

    const int tid = threadIdx.x;
    float* __restrict__ srow = g_S + (size_t)blockIdx.x * LSEQ;

    // load + monotone map + running max
    unsigned lmax = 0;
    for (int i = tid; i < LSEQ; i += 256) {
        unsigned key = f2key(srow[i]);
        keys[i] = key;
        lmax = key > lmax ? key : lmax;
    }
    sA[tid] = lmax;
    __syncthreads();
    for (int s = 128; s > 0; s >>= 1) {
        if (tid < s) sA[tid] = sA[tid] > sA[tid + s] ? sA[tid] : sA[tid + s];
        __syncthreads();
    }
    if (tid == 0) s_max = sA[0];
    __syncthreads();
    const unsigned maxkey = s_max;

    // 4-pass radix select for the TOPK-th largest key
    unsigned prefix = 0;
    unsigned kneed = TOPK;
    for (int shift = 24; shift >= 0; shift -= 8) {
        hist[tid] = 0;
        __syncthreads();
        unsigned mask_hi = (shift == 24) ? 0u : (0xFFFFFFFFu << (shift + 8));
        for (int i = tid; i < LSEQ; i += 256) {
            unsigned key = keys[i];
            if ((key & mask_hi) == prefix)
                atomicAdd(&hist[(key >> shift) & 0xFFu], 1u);
        }
        __syncthreads();
        // inclusive suffix sum over 256 bins (Hillis-Steele, ping-pong)
        sA[tid] = hist[tid];
        __syncthreads();
        unsigned* pin = sA; unsigned* pout = sB;
#pragma unroll
        for (int off = 1; off < 256; off <<= 1) {
            unsigned vv = pin[tid] + ((tid + off < 256) ? pin[tid + off] : 0u);
            pout[tid] = vv;
            __syncthreads();
            unsigned* t = pin; pin = pout; pout = t;
        }
        unsigned sufi = pin[tid];
        unsigned sufn = (tid < 255) ? pin[tid + 1] : 0u;
        if (sufi >= kneed && sufn < kneed) {
            s_sel = (unsigned)tid;
            s_kkn = kneed - sufn;
        }
        __syncthreads();
        prefix |= (s_sel << shift);
        kneed = s_kkn;
        __syncthreads();
    }
    const unsigned thr_key = prefix;
    const unsigned r = kneed;          // #elements equal to thr that belong to top-k
    const float m    = key2f(maxkey);
    const float thrf = key2f(thr_key);

    // sum of exp over strictly-greater, and count of equals
    float lsum = 0.f; unsigned leq = 0;
    for (int i = tid; i < LSEQ; i += 256) {
        unsigned key = keys[i];
        if (key > thr_key)       lsum += __expf(key2f(key) - m);
        else if (key == thr_key) leq++;
    }
    fred[tid] = lsum; sA[tid] = leq;
    __syncthreads();
    for (int s = 128; s > 0; s >>= 1) {
        if (tid < s) { fred[tid] += fred[tid + s]; sA[tid] += sA[tid + s]; }
        __syncthreads();
    }
    if (tid == 0) { s_sum = fred[0]; s_eq = sA[0]; }
    __syncthreads();

    const float eth   = __expf(thrf - m);
    const float denom = s_sum + (float)r * eth;
    const float inv   = 1.0f / denom;
    const float peq   = eth * inv;
    const bool  fast  = (s_eq == r);   // uniform across block

    for (int i = tid; i < LSEQ; i += 256) {
        unsigned key = keys[i];
        float p = 0.f;
        if (key > thr_key)              p = __expf(key2f(key) - m) * inv;
        else if (key == thr_key && fast) p = peq;
        srow[i] = p;
    }
    if (!fast) {  // rare exact-tie-at-threshold path: first r equals in index order
        __syncthreads();
        if (tid == 0) {
            unsigned cnt = 0;
            for (int i = 0; i < LSEQ; i++) {
                if (keys[i] == thr_key) {
                    if (cnt < r) srow[i] = peq;
                    cnt++;
                }
            }
        }
    }
}

// ============================================================
// ctx = P @ V per (b,h): [2048,2048] x [2048,64] -> written to [b*L+l, h*64+d]
// Tile 64x64 (N=64 full), BK=32, 256 threads, 4x4 per thread.
// ============================================================
__global__ __launch_bounds__(256) void attnv_kernel()
{
    __shared__ __align__(16) float Ps[32][64];
    __shared__ __align__(16) float Vs[32][64];
    const int tid = threadIdx.x;
    const int tx = tid & 15, ty = tid >> 4;
    const int bh = blockIdx.z, b = bh >> 4, h = bh & 15;
    const int m0 = blockIdx.x * 64;
    const float* Sb = g_S + (size_t)bh * LSEQ * LSEQ;
    const float* Vb = g_V + (size_t)b * LSEQ * DMODEL + h * DKH;

    float acc[4][4] = {};
    for (int k0 = 0; k0 < LSEQ; k0 += 32) {
#pragma unroll
        for (int i = 0; i < 2; i++) {
            int f = tid + 256 * i;      // 0..511
            int mm = f >> 3;            // row 0..63
            int c4 = (f & 7) * 4;       // col 0..28
            float4 pa = *(const float4*)(Sb + (size_t)(m0 + mm) * LSEQ + k0 + c4);
            Ps[c4 + 0][mm] = pa.x; Ps[c4 + 1][mm] = pa.y;
            Ps[c4 + 2][mm] = pa.z; Ps[c4 + 3][mm] = pa.w;
        }
#pragma unroll
        for (int i = 0; i < 2; i++) {
            int f = tid + 256 * i;
            int kkr = f >> 4;           // 0..31
            int c4  = (f & 15) * 4;     // 0..60
            *(float4*)&Vs[kkr][c4] =
                *(const float4*)(Vb + (size_t)(k0 + kkr) * DMODEL + c4);
        }
        __syncthreads();
#pragma unroll
        for (int kk = 0; kk < 32; kk++) {
            float4 av = *(const float4*)&Ps[kk][ty * 4];
            float4 bv = *(const float4*)&Vs[kk][tx * 4];
            float a4[4] = {av.x, av.y, av.z, av.w};
            float b4[4] = {bv.x, bv.y, bv.z, bv.w};
#pragma unroll
            for (int i = 0; i < 4; i++)
#pragma unroll
                for (int j = 0; j < 4; j++)
                    acc[i][j] += a4[i] * b4[j];
        }
        __syncthreads();
    }
    float* Cb = g_ctx + (size_t)b * LSEQ * DMODEL + h * DKH;
#pragma unroll
    for (int i = 0; i < 4; i++) {
        float4 o = {acc[i][0], acc[i][1], acc[i][2], acc[i][3]};
        *(float4*)(Cb + (size_t)(m0 + ty * 4 + i) * DMODEL + tx * 4) = o;
    }
}

// ============================================================
extern "C" void kernel_launch(void* const* d_in, const int* in_sizes, int n_in,
                              void* d_out, int out_size)
{
    const float* q  = (const float*)d_in[0];
    const float* k  = (const float*)d_in[1];
    const float* v  = (const float*)d_in[2];
    const float* Wq = (const float*)d_in[3];
    const float* bq = (const float*)d_in[4];
    const float* Wk = (const float*)d_in[5];
    const float* bk = (const float*)d_in[6];
    const float* Wv = (const float*)d_in[7];
    const float* bv = (const float*)d_in[8];
    const float* Wo = (const float*)d_in[9];
    const float* bo = (const float*)d_in[10];
    float* out = (float*)d_out;

    // Resolve scratch symbol addresses once (host-side; not a stream op, but
    // keep it out of the steady-state capture path anyway).
    static float *gQ = nullptr, *gK = nullptr, *gV = nullptr, *gC = nullptr;
    if (!gQ) {
        cudaGetSymbolAddress((void**)&gQ, g_Q);
        cudaGetSymbolAddress((void**)&gK, g_K);
        cudaGetSymbolAddress((void**)&gV, g_V);
        cudaGetSymbolAddress((void**)&gC, g_ctx);
    }

    dim3 blk(256);
    dim3 gproj(DMODEL / 64, BLM / 64);            // (16, 64)
    gemm_xwT_bias<<<gproj, blk>>>(q, Wq, bq, gQ);
    gemm_xwT_bias<<<gproj, blk>>>(k, Wk, bk, gK);
    gemm_xwT_bias<<<gproj, blk>>>(v, Wv, bv, gV);

    dim3 gsc(LSEQ / 64, LSEQ / 64, BHN);          // (32, 32, 32)
    scores_kernel<<<gsc, blk>>>();

    topk_softmax_kernel<<<BHN * LSEQ, blk>>>();   // 65536 blocks

    dim3 gav(LSEQ / 64, 1, BHN);                  // (32, 1, 32)
    attnv_kernel<<<gav, blk>>>();

    gemm_xwT_bias<<<gproj, blk>>>(gC, Wo, bo, out);
}

// round 5
// speedup vs baseline: 1.2768x; 1.2768x over previous
#include <cuda_runtime.h>

#define BATCH   2
#define LSEQ    2048
#define DMODEL  1024
#define NHEADS  16
#define DKH     64
#define BHN     (BATCH * NHEADS)     // 32
#define BLM     (BATCH * LSEQ)       // 4096
#define TOPK    (LSEQ / 2)           // 1024

// ---- scratch (static device arrays; allocation-free per harness rules) ----
__device__ float g_Q[(size_t)BLM * DMODEL];
__device__ float g_K[(size_t)BLM * DMODEL];
__device__ float g_V[(size_t)BLM * DMODEL];
__device__ float g_ctx[(size_t)BLM * DMODEL];
__device__ float g_S[(size_t)BHN * LSEQ * LSEQ];   // 537 MB scores/probs

// monotone float<->uint mapping (order-preserving)
__device__ __forceinline__ unsigned f2key(float f) {
    unsigned u = __float_as_uint(f);
    return (u & 0x80000000u) ? ~u : (u | 0x80000000u);
}
__device__ __forceinline__ float key2f(unsigned key) {
    unsigned u = (key & 0x80000000u) ? (key ^ 0x80000000u) : ~key;
    return __uint_as_float(u);
}

// ============================================================
// GEMM: Y[m,n] = sum_k X[m,k]*W[n,k] + bias[n]
// 128x128 tile, BK=16, 256 threads, 8x8 per thread, reg prefetch.
// ============================================================
#define GP 132
__global__ __launch_bounds__(256) void gemm128(
    const float* __restrict__ X, const float* __restrict__ W,
    const float* __restrict__ bias, float* __restrict__ Y)
{
    __shared__ __align__(16) float Xs[16 * GP];
    __shared__ __align__(16) float Ws[16 * GP];
    const int tid = threadIdx.x;
    const int tx = tid & 15, ty = tid >> 4;          // 16 x 16 thread grid
    const int m0 = blockIdx.y * 128, n0 = blockIdx.x * 128;

    const int lm0  = tid >> 2;                 // 0..63
    const int lm1  = lm0 + 64;                 // 64..127
    const int lc4  = (tid & 3) * 4;            // 0,4,8,12

    const float* Xb = X + (size_t)m0 * DMODEL;
    const float* Wb = W + (size_t)n0 * DMODEL;

    float4 px0 = *(const float4*)(Xb + (size_t)lm0 * DMODEL + lc4);
    float4 px1 = *(const float4*)(Xb + (size_t)lm1 * DMODEL + lc4);
    float4 pw0 = *(const float4*)(Wb + (size_t)lm0 * DMODEL + lc4);
    float4 pw1 = *(const float4*)(Wb + (size_t)lm1 * DMODEL + lc4);

    float acc[8][8] = {};
    for (int k0 = 0; k0 < DMODEL; k0 += 16) {
        Xs[(lc4 + 0) * GP + lm0] = px0.x; Xs[(lc4 + 1) * GP + lm0] = px0.y;
        Xs[(lc4 + 2) * GP + lm0] = px0.z; Xs[(lc4 + 3) * GP + lm0] = px0.w;
        Xs[(lc4 + 0) * GP + lm1] = px1.x; Xs[(lc4 + 1) * GP + lm1] = px1.y;
        Xs[(lc4 + 2) * GP + lm1] = px1.z; Xs[(lc4 + 3) * GP + lm1] = px1.w;
        Ws[(lc4 + 0) * GP + lm0] = pw0.x; Ws[(lc4 + 1) * GP + lm0] = pw0.y;
        Ws[(lc4 + 2) * GP + lm0] = pw0.z; Ws[(lc4 + 3) * GP + lm0] = pw0.w;
        Ws[(lc4 + 0) * GP + lm1] = pw1.x; Ws[(lc4 + 1) * GP + lm1] = pw1.y;
        Ws[(lc4 + 2) * GP + lm1] = pw1.z; Ws[(lc4 + 3) * GP + lm1] = pw1.w;
        __syncthreads();
        if (k0 + 16 < DMODEL) {
            int kn = k0 + 16 + lc4;
            px0 = *(const float4*)(Xb + (size_t)lm0 * DMODEL + kn);
            px1 = *(const float4*)(Xb + (size_t)lm1 * DMODEL + kn);
            pw0 = *(const float4*)(Wb + (size_t)lm0 * DMODEL + kn);
            pw1 = *(const float4*)(Wb + (size_t)lm1 * DMODEL + kn);
        }
#pragma unroll 8
        for (int kk = 0; kk < 16; kk++) {
            float4 a0 = *(const float4*)&Xs[kk * GP + ty * 8];
            float4 a1 = *(const float4*)&Xs[kk * GP + ty * 8 + 4];
            float4 b0 = *(const float4*)&Ws[kk * GP + tx * 8];
            float4 b1 = *(const float4*)&Ws[kk * GP + tx * 8 + 4];
            float a8[8] = {a0.x, a0.y, a0.z, a0.w, a1.x, a1.y, a1.z, a1.w};
            float b8[8] = {b0.x, b0.y, b0.z, b0.w, b1.x, b1.y, b1.z, b1.w};
#pragma unroll
            for (int i = 0; i < 8; i++)
#pragma unroll
                for (int j = 0; j < 8; j++)
                    acc[i][j] += a8[i] * b8[j];
        }
        __syncthreads();
    }
    float4 bb0 = *(const float4*)(bias + n0 + tx * 8);
    float4 bb1 = *(const float4*)(bias + n0 + tx * 8 + 4);
#pragma unroll
    for (int i = 0; i < 8; i++) {
        float* yr = Y + (size_t)(m0 + ty * 8 + i) * DMODEL + n0 + tx * 8;
        float4 o0 = {acc[i][0] + bb0.x, acc[i][1] + bb0.y,
                     acc[i][2] + bb0.z, acc[i][3] + bb0.w};
        float4 o1 = {acc[i][4] + bb1.x, acc[i][5] + bb1.y,
                     acc[i][6] + bb1.z, acc[i][7] + bb1.w};
        *(float4*)yr = o0; *(float4*)(yr + 4) = o1;
    }
}

// ============================================================
// Scores: S[bh][q][k] = (Q . K) / 8, 128x128 tile, BK=32, 8x8 per thread.
// ============================================================
__global__ __launch_bounds__(256) void scores_kernel()
{
    __shared__ __align__(16) float Qs[32 * GP];
    __shared__ __align__(16) float Ks[32 * GP];
    const int tid = threadIdx.x;
    const int tx = tid & 15, ty = tid >> 4;
    const int bh = blockIdx.z, b = bh >> 4, h = bh & 15;
    const int q0 = blockIdx.y * 128, k0 = blockIdx.x * 128;
    const float* Qb = g_Q + (size_t)b * LSEQ * DMODEL + h * DKH;
    const float* Kb = g_K + (size_t)b * LSEQ * DMODEL + h * DKH;

    float acc[8][8] = {};
    for (int kc = 0; kc < DKH; kc += 32) {
#pragma unroll
        for (int i = 0; i < 4; i++) {
            int f  = tid + 256 * i;
            int r  = f >> 3;               // 0..127
            int c4 = (f & 7) * 4;          // 0..28
            float4 qa = *(const float4*)(Qb + (size_t)(q0 + r) * DMODEL + kc + c4);
            Qs[(c4 + 0) * GP + r] = qa.x; Qs[(c4 + 1) * GP + r] = qa.y;
            Qs[(c4 + 2) * GP + r] = qa.z; Qs[(c4 + 3) * GP + r] = qa.w;
            float4 ka = *(const float4*)(Kb + (size_t)(k0 + r) * DMODEL + kc + c4);
            Ks[(c4 + 0) * GP + r] = ka.x; Ks[(c4 + 1) * GP + r] = ka.y;
            Ks[(c4 + 2) * GP + r] = ka.z; Ks[(c4 + 3) * GP + r] = ka.w;
        }
        __syncthreads();
#pragma unroll 8
        for (int kk = 0; kk < 32; kk++) {
            float4 a0 = *(const float4*)&Qs[kk * GP + ty * 8];
            float4 a1 = *(const float4*)&Qs[kk * GP + ty * 8 + 4];
            float4 b0 = *(const float4*)&Ks[kk * GP + tx * 8];
            float4 b1 = *(const float4*)&Ks[kk * GP + tx * 8 + 4];
            float a8[8] = {a0.x, a0.y, a0.z, a0.w, a1.x, a1.y, a1.z, a1.w};
            float b8[8] = {b0.x, b0.y, b0.z, b0.w, b1.x, b1.y, b1.z, b1.w};
#pragma unroll
            for (int i = 0; i < 8; i++)
#pragma unroll
                for (int j = 0; j < 8; j++)
                    acc[i][j] += a8[i] * b8[j];
        }
        __syncthreads();
    }
    float* Sb = g_S + (size_t)bh * LSEQ * LSEQ;
#pragma unroll
    for (int i = 0; i < 8; i++) {
        float* sr = Sb + (size_t)(q0 + ty * 8 + i) * LSEQ + k0 + tx * 8;
        float4 o0 = {acc[i][0] * 0.125f, acc[i][1] * 0.125f,
                     acc[i][2] * 0.125f, acc[i][3] * 0.125f};
        float4 o1 = {acc[i][4] * 0.125f, acc[i][5] * 0.125f,
                     acc[i][6] * 0.125f, acc[i][7] * 0.125f};
        *(float4*)sr = o0; *(float4*)(sr + 4) = o1;
    }
}

// ============================================================
// Per-row top-k threshold (radix select) + softmax over selected set.
// ============================================================
__global__ __launch_bounds__(256) void topk_softmax_kernel()
{
    __shared__ unsigned keys[LSEQ];
    __shared__ unsigned hist[256];
    __shared__ unsigned sA[256], sB[256];
    __shared__ float    fred[256];
    __shared__ unsigned s_sel, s_kkn, s_max, s_eq;
    __shared__ float    s_sum;

    const int tid = threadIdx.x;
    float* __restrict__ srow = g_S + (size_t)blockIdx.x * LSEQ;

    unsigned lmax = 0;
    for (int i = tid; i < LSEQ; i += 256) {
        unsigned key = f2key(srow[i]);
        keys[i] = key;
        lmax = key > lmax ? key : lmax;
    }
    sA[tid] = lmax;
    __syncthreads();
    for (int s = 128; s > 0; s >>= 1) {
        if (tid < s) sA[tid] = sA[tid] > sA[tid + s] ? sA[tid] : sA[tid + s];
        __syncthreads();
    }
    if (tid == 0) s_max = sA[0];
    __syncthreads();
    const unsigned maxkey = s_max;

    unsigned prefix = 0;
    unsigned kneed = TOPK;
    for (int shift = 24; shift >= 0; shift -= 8) {
        hist[tid] = 0;
        __syncthreads();
        unsigned mask_hi = (shift == 24) ? 0u : (0xFFFFFFFFu << (shift + 8));
        for (int i = tid; i < LSEQ; i += 256) {
            unsigned key = keys[i];
            if ((key & mask_hi) == prefix)
                atomicAdd(&hist[(key >> shift) & 0xFFu], 1u);
        }
        __syncthreads();
        sA[tid] = hist[tid];
        __syncthreads();
        unsigned* pin = sA; unsigned* pout = sB;
        for (int off = 1; off < 256; off <<= 1) {
            unsigned vv = pin[tid] + ((tid + off < 256) ? pin[tid + off] : 0u);
            pout[tid] = vv;
            __syncthreads();
            unsigned* t = pin; pin = pout; pout = t;
        }
        unsigned sufi = pin[tid];
        unsigned sufn = (tid < 255) ? pin[tid + 1] : 0u;
        if (sufi >= kneed && sufn < kneed) {
            s_sel = (unsigned)tid;
            s_kkn = kneed - sufn;
        }
        __syncthreads();
        prefix |= (s_sel << shift);
        kneed = s_kkn;
        __syncthreads();
    }
    const unsigned thr_key = prefix;
    const unsigned r = kneed;
    const float m    = key2f(maxkey);
    const float thrf = key2f(thr_key);

    float lsum = 0.f; unsigned leq = 0;
    for (int i = tid; i < LSEQ; i += 256) {
        unsigned key = keys[i];
        if (key > thr_key)       lsum += __expf(key2f(key) - m);
        else if (key == thr_key) leq++;
    }
    fred[tid] = lsum; sA[tid] = leq;
    __syncthreads();
    for (int s = 128; s > 0; s >>= 1) {
        if (tid < s) { fred[tid] += fred[tid + s]; sA[tid] += sA[tid + s]; }
        __syncthreads();
    }
    if (tid == 0) { s_sum = fred[0]; s_eq = sA[0]; }
    __syncthreads();

    const float eth   = __expf(thrf - m);
    const float denom = s_sum + (float)r * eth;
    const float inv   = 1.0f / denom;
    const float peq   = eth * inv;
    const bool  fast  = (s_eq == r);

    for (int i = tid; i < LSEQ; i += 256) {
        unsigned key = keys[i];
        float p = 0.f;
        if (key > thr_key)               p = __expf(key2f(key) - m) * inv;
        else if (key == thr_key && fast) p = peq;
        srow[i] = p;
    }
    if (!fast) {
        __syncthreads();
        if (tid == 0) {
            unsigned cnt = 0;
            for (int i = 0; i < LSEQ; i++) {
                if (keys[i] == thr_key) {
                    if (cnt < r) srow[i] = peq;
                    cnt++;
                }
            }
        }
    }
}

// ============================================================
// ctx = P @ V per (b,h): [2048,2048] x [2048,64]
// Tile 256x64, BK=32, 256 threads, 8x8 per thread.
// ============================================================
#define PP 260
#define VP 68
__global__ __launch_bounds__(256) void attnv_kernel()
{
    __shared__ __align__(16) float Ps[32 * PP];
    __shared__ __align__(16) float Vs[32 * VP];
    const int tid = threadIdx.x;
    const int tx = tid & 7, ty = tid >> 3;       // 8 x 32 thread grid
    const int bh = blockIdx.z, b = bh >> 4, h = bh & 15;
    const int m0 = blockIdx.x * 256;
    const float* Sb = g_S + (size_t)bh * LSEQ * LSEQ;
    const float* Vb = g_V + (size_t)b * LSEQ * DMODEL + h * DKH;

    float acc[8][8] = {};
    for (int k0 = 0; k0 < LSEQ; k0 += 32) {
#pragma unroll
        for (int i = 0; i < 8; i++) {
            int f  = tid + 256 * i;
            int r  = f >> 3;               // 0..255
            int c4 = (f & 7) * 4;          // 0..28
            float4 pa = *(const float4*)(Sb + (size_t)(m0 + r) * LSEQ + k0 + c4);
            Ps[(c4 + 0) * PP + r] = pa.x; Ps[(c4 + 1) * PP + r] = pa.y;
            Ps[(c4 + 2) * PP + r] = pa.z; Ps[(c4 + 3) * PP + r] = pa.w;
        }
#pragma unroll
        for (int i = 0; i < 2; i++) {
            int f   = tid + 256 * i;
            int vr  = f >> 4;              // 0..31
            int vc4 = (f & 15) * 4;        // 0..60
            *(float4*)&Vs[vr * VP + vc4] =
                *(const float4*)(Vb + (size_t)(k0 + vr) * DMODEL + vc4);
        }
        __syncthreads();
#pragma unroll 8
        for (int kk = 0; kk < 32; kk++) {
            float4 a0 = *(const float4*)&Ps[kk * PP + ty * 8];
            float4 a1 = *(const float4*)&Ps[kk * PP + ty * 8 + 4];
            float4 b0 = *(const float4*)&Vs[kk * VP + tx * 8];
            float4 b1 = *(const float4*)&Vs[kk * VP + tx * 8 + 4];
            float a8[8] = {a0.x, a0.y, a0.z, a0.w, a1.x, a1.y, a1.z, a1.w};
            float b8[8] = {b0.x, b0.y, b0.z, b0.w, b1.x, b1.y, b1.z, b1.w};
#pragma unroll
            for (int i = 0; i < 8; i++)
#pragma unroll
                for (int j = 0; j < 8; j++)
                    acc[i][j] += a8[i] * b8[j];
        }
        __syncthreads();
    }
    float* Cb = g_ctx + (size_t)b * LSEQ * DMODEL + h * DKH;
#pragma unroll
    for (int i = 0; i < 8; i++) {
        float* cr = Cb + (size_t)(m0 + ty * 8 + i) * DMODEL + tx * 8;
        float4 o0 = {acc[i][0], acc[i][1], acc[i][2], acc[i][3]};
        float4 o1 = {acc[i][4], acc[i][5], acc[i][6], acc[i][7]};
        *(float4*)cr = o0; *(float4*)(cr + 4) = o1;
    }
}

// ============================================================
extern "C" void kernel_launch(void* const* d_in, const int* in_sizes, int n_in,
                              void* d_out, int out_size)
{
    const float* q  = (const float*)d_in[0];
    const float* k  = (const float*)d_in[1];
    const float* v  = (const float*)d_in[2];
    const float* Wq = (const float*)d_in[3];
    const float* bq = (const float*)d_in[4];
    const float* Wk = (const float*)d_in[5];
    const float* bk = (const float*)d_in[6];
    const float* Wv = (const float*)d_in[7];
    const float* bv = (const float*)d_in[8];
    const float* Wo = (const float*)d_in[9];
    const float* bo = (const float*)d_in[10];
    float* out = (float*)d_out;

    static float *gQ = nullptr, *gK = nullptr, *gV = nullptr, *gC = nullptr;
    if (!gQ) {
        cudaGetSymbolAddress((void**)&gQ, g_Q);
        cudaGetSymbolAddress((void**)&gK, g_K);
        cudaGetSymbolAddress((void**)&gV, g_V);
        cudaGetSymbolAddress((void**)&gC, g_ctx);
    }

    dim3 blk(256);
    dim3 gproj(DMODEL / 128, BLM / 128);          // (8, 32)
    gemm128<<<gproj, blk>>>(q, Wq, bq, gQ);
    gemm128<<<gproj, blk>>>(k, Wk, bk, gK);
    gemm128<<<gproj, blk>>>(v, Wv, bv, gV);

    dim3 gsc(LSEQ / 128, LSEQ / 128, BHN);        // (16, 16, 32)
    scores_kernel<<<gsc, blk>>>();

    topk_softmax_kernel<<<BHN * LSEQ, blk>>>();   // 65536 blocks

    dim3 gav(LSEQ / 256, 1, BHN);                 // (8, 1, 32)
    attnv_kernel<<<gav, blk>>>();

    gemm128<<<gproj, blk>>>(gC, Wo, bo, out);
}

// round 6
// speedup vs baseline: 1.2921x; 1.0120x over previous
#include <cuda_runtime.h>

#define BATCH   2
#define LSEQ    2048
#define DMODEL  1024
#define NHEADS  16
#define DKH     64
#define BHN     (BATCH * NHEADS)     // 32
#define BLM     (BATCH * LSEQ)       // 4096
#define TOPK    (LSEQ / 2)           // 1024

// ---- scratch (static device arrays; allocation-free per harness rules) ----
__device__ float g_Q[(size_t)BLM * DMODEL];
__device__ float g_K[(size_t)BLM * DMODEL];
__device__ float g_V[(size_t)BLM * DMODEL];
__device__ float g_ctx[(size_t)BLM * DMODEL];
__device__ float g_S[(size_t)BHN * LSEQ * LSEQ];   // 537 MB scores/probs

// monotone float<->uint mapping (order-preserving)
__device__ __forceinline__ unsigned f2key(float f) {
    unsigned u = __float_as_uint(f);
    return (u & 0x80000000u) ? ~u : (u | 0x80000000u);
}
__device__ __forceinline__ float key2f(unsigned key) {
    unsigned u = (key & 0x80000000u) ? (key ^ 0x80000000u) : ~key;
    return __uint_as_float(u);
}

struct GemmPtrs { const float* X; const float* W; const float* B; float* Y; };

// ============================================================
// Shared GEMM body: Y[m,n] = sum_k X[m,k]*W[n,k] + bias[n]
// 128x128 tile, BK=8, double-buffered smem, 1 sync per stage,
// 256 threads, 8x8 per thread.
// ============================================================
__device__ __forceinline__ void gemm_body(
    const float* __restrict__ X, const float* __restrict__ W,
    const float* __restrict__ B, float* __restrict__ Y,
    int m0, int n0)
{
    __shared__ __align__(16) float As[2][8][128];
    __shared__ __align__(16) float Bs[2][8][128];
    const int tid = threadIdx.x;
    const int lr  = tid >> 1;          // 0..127 tile row
    const int lc  = (tid & 1) * 4;     // 0 or 4 (k within stage)
    const int tx  = tid & 15, ty = tid >> 4;

    const float* Xb = X + (size_t)(m0 + lr) * DMODEL + lc;
    const float* Wb = W + (size_t)(n0 + lr) * DMODEL + lc;

    // prologue: stage 0
    {
        float4 xr = *(const float4*)Xb;
        float4 wr = *(const float4*)Wb;
        As[0][lc + 0][lr] = xr.x; As[0][lc + 1][lr] = xr.y;
        As[0][lc + 2][lr] = xr.z; As[0][lc + 3][lr] = xr.w;
        Bs[0][lc + 0][lr] = wr.x; Bs[0][lc + 1][lr] = wr.y;
        Bs[0][lc + 2][lr] = wr.z; Bs[0][lc + 3][lr] = wr.w;
    }
    __syncthreads();

    float acc[8][8] = {};
    int rb = 0;
    for (int k0 = 0; k0 < DMODEL; k0 += 8) {
        const bool nxt = (k0 + 8) < DMODEL;
        float4 xn, wn;
        if (nxt) {
            xn = *(const float4*)(Xb + k0 + 8);
            wn = *(const float4*)(Wb + k0 + 8);
        }
#pragma unroll
        for (int kk = 0; kk < 8; kk++) {
            float4 a0 = *(const float4*)&As[rb][kk][ty * 8];
            float4 a1 = *(const float4*)&As[rb][kk][ty * 8 + 4];
            float4 b0 = *(const float4*)&Bs[rb][kk][tx * 8];
            float4 b1 = *(const float4*)&Bs[rb][kk][tx * 8 + 4];
            float a8[8] = {a0.x, a0.y, a0.z, a0.w, a1.x, a1.y, a1.z, a1.w};
            float b8[8] = {b0.x, b0.y, b0.z, b0.w, b1.x, b1.y, b1.z, b1.w};
#pragma unroll
            for (int i = 0; i < 8; i++)
#pragma unroll
                for (int j = 0; j < 8; j++)
                    acc[i][j] += a8[i] * b8[j];
        }
        if (nxt) {
            const int wb2 = rb ^ 1;
            As[wb2][lc + 0][lr] = xn.x; As[wb2][lc + 1][lr] = xn.y;
            As[wb2][lc + 2][lr] = xn.z; As[wb2][lc + 3][lr] = xn.w;
            Bs[wb2][lc + 0][lr] = wn.x; Bs[wb2][lc + 1][lr] = wn.y;
            Bs[wb2][lc + 2][lr] = wn.z; Bs[wb2][lc + 3][lr] = wn.w;
            __syncthreads();
            rb = wb2;
        }
    }
    float4 bb0 = *(const float4*)(B + n0 + tx * 8);
    float4 bb1 = *(const float4*)(B + n0 + tx * 8 + 4);
#pragma unroll
    for (int i = 0; i < 8; i++) {
        float* yr = Y + (size_t)(m0 + ty * 8 + i) * DMODEL + n0 + tx * 8;
        float4 o0 = {acc[i][0] + bb0.x, acc[i][1] + bb0.y,
                     acc[i][2] + bb0.z, acc[i][3] + bb0.w};
        float4 o1 = {acc[i][4] + bb1.x, acc[i][5] + bb1.y,
                     acc[i][6] + bb1.z, acc[i][7] + bb1.w};
        *(float4*)yr = o0; *(float4*)(yr + 4) = o1;
    }
}

// fused Q/K/V projections: blockIdx.z selects the matrix triple
__global__ __launch_bounds__(256) void gemm_qkv_kernel(GemmPtrs a, GemmPtrs b, GemmPtrs c)
{
    GemmPtrs g = (blockIdx.z == 0) ? a : (blockIdx.z == 1) ? b : c;
    gemm_body(g.X, g.W, g.B, g.Y, blockIdx.y * 128, blockIdx.x * 128);
}

__global__ __launch_bounds__(256) void gemm_one_kernel(
    const float* __restrict__ X, const float* __restrict__ W,
    const float* __restrict__ B, float* __restrict__ Y)
{
    gemm_body(X, W, B, Y, blockIdx.y * 128, blockIdx.x * 128);
}

// ============================================================
// Scores: S[bh][q][k] = (Q . K) / 8
// 128x128 tile, BK=8 double-buffered over d_k=64, 8x8 per thread.
// ============================================================
__global__ __launch_bounds__(256) void scores_kernel()
{
    __shared__ __align__(16) float Qs[2][8][128];
    __shared__ __align__(16) float Ks[2][8][128];
    const int tid = threadIdx.x;
    const int lr  = tid >> 1;
    const int lc  = (tid & 1) * 4;
    const int tx  = tid & 15, ty = tid >> 4;
    const int bh = blockIdx.z, b = bh >> 4, h = bh & 15;
    const int q0 = blockIdx.y * 128, k0 = blockIdx.x * 128;

    const float* Qb = g_Q + (size_t)(b * LSEQ + q0 + lr) * DMODEL + h * DKH + lc;
    const float* Kb = g_K + (size_t)(b * LSEQ + k0 + lr) * DMODEL + h * DKH + lc;

    {
        float4 qr = *(const float4*)Qb;
        float4 kr = *(const float4*)Kb;
        Qs[0][lc + 0][lr] = qr.x; Qs[0][lc + 1][lr] = qr.y;
        Qs[0][lc + 2][lr] = qr.z; Qs[0][lc + 3][lr] = qr.w;
        Ks[0][lc + 0][lr] = kr.x; Ks[0][lc + 1][lr] = kr.y;
        Ks[0][lc + 2][lr] = kr.z; Ks[0][lc + 3][lr] = kr.w;
    }
    __syncthreads();

    float acc[8][8] = {};
    int rb = 0;
    for (int kc = 0; kc < DKH; kc += 8) {
        const bool nxt = (kc + 8) < DKH;
        float4 qn, kn;
        if (nxt) {
            qn = *(const float4*)(Qb + kc + 8);
            kn = *(const float4*)(Kb + kc + 8);
        }
#pragma unroll
        for (int kk = 0; kk < 8; kk++) {
            float4 a0 = *(const float4*)&Qs[rb][kk][ty * 8];
            float4 a1 = *(const float4*)&Qs[rb][kk][ty * 8 + 4];
            float4 b0 = *(const float4*)&Ks[rb][kk][tx * 8];
            float4 b1 = *(const float4*)&Ks[rb][kk][tx * 8 + 4];
            float a8[8] = {a0.x, a0.y, a0.z, a0.w, a1.x, a1.y, a1.z, a1.w};
            float b8[8] = {b0.x, b0.y, b0.z, b0.w, b1.x, b1.y, b1.z, b1.w};
#pragma unroll
            for (int i = 0; i < 8; i++)
#pragma unroll
                for (int j = 0; j < 8; j++)
                    acc[i][j] += a8[i] * b8[j];
        }
        if (nxt) {
            const int wb2 = rb ^ 1;
            Qs[wb2][lc + 0][lr] = qn.x; Qs[wb2][lc + 1][lr] = qn.y;
            Qs[wb2][lc + 2][lr] = qn.z; Qs[wb2][lc + 3][lr] = qn.w;
            Ks[wb2][lc + 0][lr] = kn.x; Ks[wb2][lc + 1][lr] = kn.y;
            Ks[wb2][lc + 2][lr] = kn.z; Ks[wb2][lc + 3][lr] = kn.w;
            __syncthreads();
            rb = wb2;
        }
    }
    float* Sb = g_S + (size_t)bh * LSEQ * LSEQ;
#pragma unroll
    for (int i = 0; i < 8; i++) {
        float* sr = Sb + (size_t)(q0 + ty * 8 + i) * LSEQ + k0 + tx * 8;
        float4 o0 = {acc[i][0] * 0.125f, acc[i][1] * 0.125f,
                     acc[i][2] * 0.125f, acc[i][3] * 0.125f};
        float4 o1 = {acc[i][4] * 0.125f, acc[i][5] * 0.125f,
                     acc[i][6] * 0.125f, acc[i][7] * 0.125f};
        *(float4*)sr = o0; *(float4*)(sr + 4) = o1;
    }
}

// ============================================================
// Per-row top-k threshold (radix select) + softmax, warp-shuffle scans.
// ============================================================
__global__ __launch_bounds__(256) void topk_softmax_kernel()
{
    __shared__ unsigned keys[LSEQ];
    __shared__ unsigned hist[256];
    __shared__ unsigned warp_u[8];
    __shared__ float    warp_f[8];
    __shared__ unsigned s_sel, s_kkn, s_max, s_eq;
    __shared__ float    s_sum;

    const int tid  = threadIdx.x;
    const int lane = tid & 31, wid = tid >> 5;
    float* __restrict__ srow = g_S + (size_t)blockIdx.x * LSEQ;

    // load + monotone map + max
    unsigned lmax = 0;
    for (int i = tid; i < LSEQ; i += 256) {
        unsigned key = f2key(srow[i]);
        keys[i] = key;
        lmax = key > lmax ? key : lmax;
    }
#pragma unroll
    for (int off = 16; off > 0; off >>= 1) {
        unsigned o = __shfl_xor_sync(0xffffffffu, lmax, off);
        lmax = o > lmax ? o : lmax;
    }
    if (lane == 0) warp_u[wid] = lmax;
    __syncthreads();                       // keys + warp maxima visible
    if (tid == 0) {
        unsigned m = warp_u[0];
#pragma unroll
        for (int w = 1; w < 8; w++) m = warp_u[w] > m ? warp_u[w] : m;
        s_max = m;
    }
    __syncthreads();
    const unsigned maxkey = s_max;

    // 4-pass radix select (8-bit digits) for the TOPK-th largest key
    unsigned prefix = 0;
    unsigned kneed  = TOPK;
    for (int shift = 24; shift >= 0; shift -= 8) {
        hist[tid] = 0;
        __syncthreads();
        unsigned mask_hi = (shift == 24) ? 0u : (0xFFFFFFFFu << (shift + 8));
        for (int i = tid; i < LSEQ; i += 256) {
            unsigned key = keys[i];
            if ((key & mask_hi) == prefix)
                atomicAdd(&hist[(key >> shift) & 0xFFu], 1u);
        }
        __syncthreads();
        const unsigned h = hist[tid];
        // inclusive suffix scan within warp (lane i gets sum over lanes >= i)
        unsigned v = h;
#pragma unroll
        for (int off = 1; off < 32; off <<= 1) {
            unsigned t = __shfl_down_sync(0xffffffffu, v, off);
            if (lane + off < 32) v += t;
        }
        if (lane == 0) warp_u[wid] = v;    // warp total
        __syncthreads();
        unsigned wtail = 0;
#pragma unroll
        for (int w = 0; w < 8; w++) if (w > wid) wtail += warp_u[w];
        const unsigned sufi = v + wtail;   // inclusive suffix over bins tid..255
        const unsigned sufn = sufi - h;    // suffix over bins > tid
        if (sufi >= kneed && sufn < kneed) {
            s_sel = (unsigned)tid;
            s_kkn = kneed - sufn;
        }
        __syncthreads();
        prefix |= (s_sel << shift);
        kneed = s_kkn;
        // next write to s_sel is separated by two barriers above -> no extra sync
    }
    const unsigned thr_key = prefix;
    const unsigned r = kneed;              // #threshold-equal elements in top-k
    const float m    = key2f(maxkey);
    const float thrf = key2f(thr_key);

    // sum of exp over strictly-greater, count of equals
    float lsum = 0.f; unsigned leq = 0;
    for (int i = tid; i < LSEQ; i += 256) {
        unsigned key = keys[i];
        if (key > thr_key)       lsum += __expf(key2f(key) - m);
        else if (key == thr_key) leq++;
    }
#pragma unroll
    for (int off = 16; off > 0; off >>= 1) {
        lsum += __shfl_xor_sync(0xffffffffu, lsum, off);
        leq  += __shfl_xor_sync(0xffffffffu, leq,  off);
    }
    if (lane == 0) { warp_f[wid] = lsum; warp_u[wid] = leq; }
    __syncthreads();
    if (tid == 0) {
        float fs = 0.f; unsigned ue = 0;
#pragma unroll
        for (int w = 0; w < 8; w++) { fs += warp_f[w]; ue += warp_u[w]; }
        s_sum = fs; s_eq = ue;
    }
    __syncthreads();

    const float eth   = __expf(thrf - m);
    const float denom = s_sum + (float)r * eth;
    const float inv   = 1.0f / denom;
    const float peq   = eth * inv;
    const bool  fast  = (s_eq == r);       // uniform across block

    for (int i = tid; i < LSEQ; i += 256) {
        unsigned key = keys[i];
        float p = 0.f;
        if (key > thr_key)               p = __expf(key2f(key) - m) * inv;
        else if (key == thr_key && fast) p = peq;
        srow[i] = p;
    }
    if (!fast) {  // rare exact-tie path: first r equals in index order
        __syncthreads();
        if (tid == 0) {
            unsigned cnt = 0;
            for (int i = 0; i < LSEQ; i++) {
                if (keys[i] == thr_key) {
                    if (cnt < r) srow[i] = peq;
                    cnt++;
                }
            }
        }
    }
}

// ============================================================
// ctx = P @ V per (b,h): [2048,2048] x [2048,64]
// Tile 256x64, BK=8 double-buffered, 256 threads, 8x8 per thread.
// ============================================================
__global__ __launch_bounds__(256) void attnv_kernel()
{
    __shared__ __align__(16) float Ps[2][8][256];
    __shared__ __align__(16) float Vs[2][8][64];
    const int tid = threadIdx.x;
    const int tx = tid & 7, ty = tid >> 3;       // 8 x 32 thread grid
    const int pm = tid >> 1;                     // 0..127 (rows pm, pm+128)
    const int pc = (tid & 1) * 4;                // 0 or 4
    const int vr = tid >> 4;                     // 0..15 (use <8 via tid<128)
    const int vc = (tid & 15) * 4;               // 0..60
    const int bh = blockIdx.z, b = bh >> 4, h = bh & 15;
    const int m0 = blockIdx.x * 256;

    const float* Sb = g_S + (size_t)bh * LSEQ * LSEQ;
    const float* Pb = Sb + (size_t)m0 * LSEQ;
    const float* Vb = g_V + (size_t)b * LSEQ * DMODEL + h * DKH;

    // prologue: stage 0
    {
        float4 p0 = *(const float4*)(Pb + (size_t)pm * LSEQ + pc);
        float4 p1 = *(const float4*)(Pb + (size_t)(pm + 128) * LSEQ + pc);
        Ps[0][pc + 0][pm] = p0.x; Ps[0][pc + 1][pm] = p0.y;
        Ps[0][pc + 2][pm] = p0.z; Ps[0][pc + 3][pm] = p0.w;
        Ps[0][pc + 0][pm + 128] = p1.x; Ps[0][pc + 1][pm + 128] = p1.y;
        Ps[0][pc + 2][pm + 128] = p1.z; Ps[0][pc + 3][pm + 128] = p1.w;
        if (tid < 128) {
            float4 vv = *(const float4*)(Vb + (size_t)vr * DMODEL + vc);
            *(float4*)&Vs[0][vr][vc] = vv;
        }
    }
    __syncthreads();

    float acc[8][8] = {};
    int rb = 0;
    for (int k0 = 0; k0 < LSEQ; k0 += 8) {
        const bool nxt = (k0 + 8) < LSEQ;
        float4 p0n, p1n, vn;
        if (nxt) {
            p0n = *(const float4*)(Pb + (size_t)pm * LSEQ + k0 + 8 + pc);
            p1n = *(const float4*)(Pb + (size_t)(pm + 128) * LSEQ + k0 + 8 + pc);
            if (tid < 128)
                vn = *(const float4*)(Vb + (size_t)(k0 + 8 + vr) * DMODEL + vc);
        }
#pragma unroll
        for (int kk = 0; kk < 8; kk++) {
            float4 a0 = *(const float4*)&Ps[rb][kk][ty * 8];
            float4 a1 = *(const float4*)&Ps[rb][kk][ty * 8 + 4];
            float4 b0 = *(const float4*)&Vs[rb][kk][tx * 8];
            float4 b1 = *(const float4*)&Vs[rb][kk][tx * 8 + 4];
            float a8[8] = {a0.x, a0.y, a0.z, a0.w, a1.x, a1.y, a1.z, a1.w};
            float b8[8] = {b0.x, b0.y, b0.z, b0.w, b1.x, b1.y, b1.z, b1.w};
#pragma unroll
            for (int i = 0; i < 8; i++)
#pragma unroll
                for (int j = 0; j < 8; j++)
                    acc[i][j] += a8[i] * b8[j];
        }
        if (nxt) {
            const int wb2 = rb ^ 1;
            Ps[wb2][pc + 0][pm] = p0n.x; Ps[wb2][pc + 1][pm] = p0n.y;
            Ps[wb2][pc + 2][pm] = p0n.z; Ps[wb2][pc + 3][pm] = p0n.w;
            Ps[wb2][pc + 0][pm + 128] = p1n.x; Ps[wb2][pc + 1][pm + 128] = p1n.y;
            Ps[wb2][pc + 2][pm + 128] = p1n.z; Ps[wb2][pc + 3][pm + 128] = p1n.w;
            if (tid < 128)
                *(float4*)&Vs[wb2][vr][vc] = vn;
            __syncthreads();
            rb = wb2;
        }
    }
    float* Cb = g_ctx + (size_t)b * LSEQ * DMODEL + h * DKH;
#pragma unroll
    for (int i = 0; i < 8; i++) {
        float* cr = Cb + (size_t)(m0 + ty * 8 + i) * DMODEL + tx * 8;
        float4 o0 = {acc[i][0], acc[i][1], acc[i][2], acc[i][3]};
        float4 o1 = {acc[i][4], acc[i][5], acc[i][6], acc[i][7]};
        *(float4*)cr = o0; *(float4*)(cr + 4) = o1;
    }
}

// ============================================================
extern "C" void kernel_launch(void* const* d_in, const int* in_sizes, int n_in,
                              void* d_out, int out_size)
{
    const float* q  = (const float*)d_in[0];
    const float* k  = (const float*)d_in[1];
    const float* v  = (const float*)d_in[2];
    const float* Wq = (const float*)d_in[3];
    const float* bq = (const float*)d_in[4];
    const float* Wk = (const float*)d_in[5];
    const float* bk = (const float*)d_in[6];
    const float* Wv = (const float*)d_in[7];
    const float* bv = (const float*)d_in[8];
    const float* Wo = (const float*)d_in[9];
    const float* bo = (const float*)d_in[10];
    float* out = (float*)d_out;

    static float *gQ = nullptr, *gK = nullptr, *gV = nullptr, *gC = nullptr;
    if (!gQ) {
        cudaGetSymbolAddress((void**)&gQ, g_Q);
        cudaGetSymbolAddress((void**)&gK, g_K);
        cudaGetSymbolAddress((void**)&gV, g_V);
        cudaGetSymbolAddress((void**)&gC, g_ctx);
    }

    dim3 blk(256);

    GemmPtrs pq = {q, Wq, bq, gQ};
    GemmPtrs pk = {k, Wk, bk, gK};
    GemmPtrs pv = {v, Wv, bv, gV};
    dim3 gqkv(DMODEL / 128, BLM / 128, 3);        // (8, 32, 3)
    gemm_qkv_kernel<<<gqkv, blk>>>(pq, pk, pv);

    dim3 gsc(LSEQ / 128, LSEQ / 128, BHN);        // (16, 16, 32)
    scores_kernel<<<gsc, blk>>>();

    topk_softmax_kernel<<<BHN * LSEQ, blk>>>();   // 65536 blocks

    dim3 gav(LSEQ / 256, 1, BHN);                 // (8, 1, 32)
    attnv_kernel<<<gav, blk>>>();

    dim3 gproj(DMODEL / 128, BLM / 128);          // (8, 32)
    gemm_one_kernel<<<gproj, blk>>>(gC, Wo, bo, out);
}

// round 9
// speedup vs baseline: 1.4157x; 1.0956x over previous
#include <cuda_runtime.h>
#include <cuda_fp16.h>
#include <mma.h>

using namespace nvcuda;

#define BATCH   2
#define LSEQ    2048
#define DMODEL  1024
#define NHEADS  16
#define DKH     64
#define BHN     (BATCH * NHEADS)     // 32
#define BLM     (BATCH * LSEQ)       // 4096
#define TOPK    (LSEQ / 2)           // 1024
#define KSPLIT  3072                 // fp16x3 K-concat length

// ---- scratch (static device arrays; allocation-free per harness rules) ----
__device__ float g_Q[(size_t)BLM * DMODEL];
__device__ float g_K[(size_t)BLM * DMODEL];
__device__ float g_V[(size_t)BLM * DMODEL];
__device__ float g_ctx[(size_t)BLM * DMODEL];
__device__ float g_S[(size_t)BHN * LSEQ * LSEQ];   // 537 MB scores/probs
__device__ __half g_Asp[(size_t)BLM * KSPLIT];     // 24 MB split activations
__device__ __half g_Bsp[(size_t)DMODEL * KSPLIT];  //  6 MB split weights

// monotone float<->uint mapping (order-preserving)
__device__ __forceinline__ unsigned f2key(float f) {
    unsigned u = __float_as_uint(f);
    return (u & 0x80000000u) ? ~u : (u | 0x80000000u);
}
__device__ __forceinline__ float key2f(unsigned key) {
    unsigned u = (key & 0x80000000u) ? (key ^ 0x80000000u) : ~key;
    return __uint_as_float(u);
}

// ============================================================
// fp16x3 split kernels (Dekker 2-way split, drop al*bl term):
// X row -> [ah | ah | al], W row -> [bh | bl | bh]
// sum of products = ah*bh + ah*bl + al*bh  ~= a*b with err ~2^-21
// ============================================================
__global__ __launch_bounds__(256) void split_x_kernel(
    const float* __restrict__ X, __half* __restrict__ O, int nelem)
{
    int i = blockIdx.x * 256 + threadIdx.x;
    if (i >= nelem) return;
    int r = i >> 10, c = i & 1023;
    float a = X[i];
    __half ah = __float2half(a);
    __half al = __float2half(a - __half2float(ah));
    __half* o = O + (size_t)r * KSPLIT;
    o[c] = ah; o[1024 + c] = ah; o[2048 + c] = al;
}
__global__ __launch_bounds__(256) void split_w_kernel(
    const float* __restrict__ W, __half* __restrict__ O, int nelem)
{
    int i = blockIdx.x * 256 + threadIdx.x;
    if (i >= nelem) return;
    int r = i >> 10, c = i & 1023;
    float b = W[i];
    __half bh = __float2half(b);
    __half bl = __float2half(b - __half2float(bh));
    __half* o = O + (size_t)r * KSPLIT;
    o[c] = bh; o[1024 + c] = bl; o[2048 + c] = bh;
}

// ============================================================
// WMMA GEMM: Y[m,n] = sum_k' A'[m,k']*B'[n,k'] + bias[n]
// CTA tile 128x64, 8 warps (4x2), each warp 32x32 via 2x2 wmma 16x16x16 fp16.
// BK=32 double-buffered smem; acc initialized from bias tile.
// ============================================================
#define AST 40     // smem row stride in half elements (mult of 8, padded)
__global__ __launch_bounds__(256) void mm_wmma_kernel(
    const __half* __restrict__ A,   // [BLM][KSPLIT]
    const __half* __restrict__ Bm,  // [DMODEL][KSPLIT]
    const float* __restrict__ bias, float* __restrict__ Y)
{
    __shared__ __align__(16) __half As[2][128][AST];
    __shared__ __align__(16) __half Bs[2][64][AST];
    __shared__ __align__(16) float BiasS[16][72];

    const int tid = threadIdx.x;
    const int wid = tid >> 5;
    const int wr = wid >> 1;           // 0..3 warp-row  -> rows wr*32
    const int wc = wid & 1;            // 0..1 warp-col  -> cols wc*32
    const int m0 = blockIdx.y * 128, n0 = blockIdx.x * 64;

    // bias tile: 16 identical rows of this CTA's 64 bias values
    for (int i = tid; i < 16 * 64; i += 256) {
        int r = i >> 6, c = i & 63;
        BiasS[r][c] = bias[n0 + c];
    }

    // global load mapping
    const int ar = tid >> 2;           // 0..63 (+64): A rows
    const int au = tid & 3;            // 0..3 : 8-elem group within 32
    const int br = tid >> 2;           // 0..63 : B rows
    const __half* Ab = A + (size_t)m0 * KSPLIT;
    const __half* Bb = Bm + (size_t)n0 * KSPLIT;

    // prologue: stage 0
    {
        uint4 a0 = *(const uint4*)(Ab + (size_t)ar * KSPLIT + au * 8);
        uint4 a1 = *(const uint4*)(Ab + (size_t)(ar + 64) * KSPLIT + au * 8);
        uint4 b0 = *(const uint4*)(Bb + (size_t)br * KSPLIT + au * 8);
        *(uint4*)&As[0][ar][au * 8] = a0;
        *(uint4*)&As[0][ar + 64][au * 8] = a1;
        *(uint4*)&Bs[0][br][au * 8] = b0;
    }
    __syncthreads();

    wmma::fragment<wmma::accumulator, 16, 16, 16, float> acc[2][2];
#pragma unroll
    for (int i = 0; i < 2; i++)
#pragma unroll
        for (int j = 0; j < 2; j++)
            wmma::load_matrix_sync(acc[i][j], &BiasS[0][wc * 32 + j * 16], 72,
                                   wmma::mem_row_major);

    const int NST = KSPLIT / 32;       // 96 stages
    for (int s = 0; s < NST; s++) {
        const int buf = s & 1;
        uint4 pa0, pa1, pb0;
        const bool nxt = (s + 1) < NST;
        if (nxt) {
            int ko = (s + 1) * 32 + au * 8;
            pa0 = *(const uint4*)(Ab + (size_t)ar * KSPLIT + ko);
            pa1 = *(const uint4*)(Ab + (size_t)(ar + 64) * KSPLIT + ko);
            pb0 = *(const uint4*)(Bb + (size_t)br * KSPLIT + ko);
        }
#pragma unroll
        for (int kk = 0; kk < 32; kk += 16) {
            wmma::fragment<wmma::matrix_a, 16, 16, 16, __half, wmma::row_major> af[2];
            wmma::fragment<wmma::matrix_b, 16, 16, 16, __half, wmma::col_major> bf[2];
            wmma::load_matrix_sync(af[0], &As[buf][wr * 32][kk], AST);
            wmma::load_matrix_sync(af[1], &As[buf][wr * 32 + 16][kk], AST);
            wmma::load_matrix_sync(bf[0], &Bs[buf][wc * 32][kk], AST);
            wmma::load_matrix_sync(bf[1], &Bs[buf][wc * 32 + 16][kk], AST);
#pragma unroll
            for (int i = 0; i < 2; i++)
#pragma unroll
                for (int j = 0; j < 2; j++)
                    wmma::mma_sync(acc[i][j], af[i], bf[j], acc[i][j]);
        }
        if (nxt) {
            const int nb = buf ^ 1;
            *(uint4*)&As[nb][ar][au * 8] = pa0;
            *(uint4*)&As[nb][ar + 64][au * 8] = pa1;
            *(uint4*)&Bs[nb][br][au * 8] = pb0;
            __syncthreads();
        }
    }

#pragma unroll
    for (int i = 0; i < 2; i++)
#pragma unroll
        for (int j = 0; j < 2; j++)
            wmma::store_matrix_sync(
                Y + (size_t)(m0 + wr * 32 + i * 16) * DMODEL + n0 + wc * 32 + j * 16,
                acc[i][j], DMODEL, wmma::mem_row_major);
}

// ============================================================
// Scores: S[bh][q][k] = (Q . K) / 8 (fp32 SIMT, unchanged)
// ============================================================
__global__ __launch_bounds__(256) void scores_kernel()
{
    __shared__ __align__(16) float Qs[2][8][128];
    __shared__ __align__(16) float Ks[2][8][128];
    const int tid = threadIdx.x;
    const int lr  = tid >> 1;
    const int lc  = (tid & 1) * 4;
    const int tx  = tid & 15, ty = tid >> 4;
    const int bh = blockIdx.z, b = bh >> 4, h = bh & 15;
    const int q0 = blockIdx.y * 128, k0 = blockIdx.x * 128;

    const float* Qb = g_Q + (size_t)(b * LSEQ + q0 + lr) * DMODEL + h * DKH + lc;
    const float* Kb = g_K + (size_t)(b * LSEQ + k0 + lr) * DMODEL + h * DKH + lc;

    {
        float4 qr = *(const float4*)Qb;
        float4 kr = *(const float4*)Kb;
        Qs[0][lc + 0][lr] = qr.x; Qs[0][lc + 1][lr] = qr.y;
        Qs[0][lc + 2][lr] = qr.z; Qs[0][lc + 3][lr] = qr.w;
        Ks[0][lc + 0][lr] = kr.x; Ks[0][lc + 1][lr] = kr.y;
        Ks[0][lc + 2][lr] = kr.z; Ks[0][lc + 3][lr] = kr.w;
    }
    __syncthreads();

    float acc[8][8] = {};
    int rb = 0;
    for (int kc = 0; kc < DKH; kc += 8) {
        const bool nxt = (kc + 8) < DKH;
        float4 qn, kn;
        if (nxt) {
            qn = *(const float4*)(Qb + kc + 8);
            kn = *(const float4*)(Kb + kc + 8);
        }
#pragma unroll
        for (int kk = 0; kk < 8; kk++) {
            float4 a0 = *(const float4*)&Qs[rb][kk][ty * 8];
            float4 a1 = *(const float4*)&Qs[rb][kk][ty * 8 + 4];
            float4 b0 = *(const float4*)&Ks[rb][kk][tx * 8];
            float4 b1 = *(const float4*)&Ks[rb][kk][tx * 8 + 4];
            float a8[8] = {a0.x, a0.y, a0.z, a0.w, a1.x, a1.y, a1.z, a1.w};
            float b8[8] = {b0.x, b0.y, b0.z, b0.w, b1.x, b1.y, b1.z, b1.w};
#pragma unroll
            for (int i = 0; i < 8; i++)
#pragma unroll
                for (int j = 0; j < 8; j++)
                    acc[i][j] += a8[i] * b8[j];
        }
        if (nxt) {
            const int wb2 = rb ^ 1;
            Qs[wb2][lc + 0][lr] = qn.x; Qs[wb2][lc + 1][lr] = qn.y;
            Qs[wb2][lc + 2][lr] = qn.z; Qs[wb2][lc + 3][lr] = qn.w;
            Ks[wb2][lc + 0][lr] = kn.x; Ks[wb2][lc + 1][lr] = kn.y;
            Ks[wb2][lc + 2][lr] = kn.z; Ks[wb2][lc + 3][lr] = kn.w;
            __syncthreads();
            rb = wb2;
        }
    }
    float* Sb = g_S + (size_t)bh * LSEQ * LSEQ;
#pragma unroll
    for (int i = 0; i < 8; i++) {
        float* sr = Sb + (size_t)(q0 + ty * 8 + i) * LSEQ + k0 + tx * 8;
        float4 o0 = {acc[i][0] * 0.125f, acc[i][1] * 0.125f,
                     acc[i][2] * 0.125f, acc[i][3] * 0.125f};
        float4 o1 = {acc[i][4] * 0.125f, acc[i][5] * 0.125f,
                     acc[i][6] * 0.125f, acc[i][7] * 0.125f};
        *(float4*)sr = o0; *(float4*)(sr + 4) = o1;
    }
}

// ============================================================
// Per-row top-k threshold (radix select) + softmax (unchanged)
// ============================================================
__global__ __launch_bounds__(256) void topk_softmax_kernel()
{
    __shared__ unsigned keys[LSEQ];
    __shared__ unsigned hist[256];
    __shared__ unsigned warp_u[8];
    __shared__ float    warp_f[8];
    __shared__ unsigned s_sel, s_kkn, s_max, s_eq;
    __shared__ float    s_sum;

    const int tid  = threadIdx.x;
    const int lane = tid & 31, wid = tid >> 5;
    float* __restrict__ srow = g_S + (size_t)blockIdx.x * LSEQ;

    unsigned lmax = 0;
    for (int i = tid; i < LSEQ; i += 256) {
        unsigned key = f2key(srow[i]);
        keys[i] = key;
        lmax = key > lmax ? key : lmax;
    }
#pragma unroll
    for (int off = 16; off > 0; off >>= 1) {
        unsigned o = __shfl_xor_sync(0xffffffffu, lmax, off);
        lmax = o > lmax ? o : lmax;
    }
    if (lane == 0) warp_u[wid] = lmax;
    __syncthreads();
    if (tid == 0) {
        unsigned m = warp_u[0];
#pragma unroll
        for (int w = 1; w < 8; w++) m = warp_u[w] > m ? warp_u[w] : m;
        s_max = m;
    }
    __syncthreads();
    const unsigned maxkey = s_max;

    unsigned prefix = 0;
    unsigned kneed  = TOPK;
    for (int shift = 24; shift >= 0; shift -= 8) {
        hist[tid] = 0;
        __syncthreads();
        unsigned mask_hi = (shift == 24) ? 0u : (0xFFFFFFFFu << (shift + 8));
        for (int i = tid; i < LSEQ; i += 256) {
            unsigned key = keys[i];
            if ((key & mask_hi) == prefix)
                atomicAdd(&hist[(key >> shift) & 0xFFu], 1u);
        }
        __syncthreads();
        const unsigned h = hist[tid];
        unsigned v = h;
#pragma unroll
        for (int off = 1; off < 32; off <<= 1) {
            unsigned t = __shfl_down_sync(0xffffffffu, v, off);
            if (lane + off < 32) v += t;
        }
        if (lane == 0) warp_u[wid] = v;
        __syncthreads();
        unsigned wtail = 0;
#pragma unroll
        for (int w = 0; w < 8; w++) if (w > wid) wtail += warp_u[w];
        const unsigned sufi = v + wtail;
        const unsigned sufn = sufi - h;
        if (sufi >= kneed && sufn < kneed) {
            s_sel = (unsigned)tid;
            s_kkn = kneed - sufn;
        }
        __syncthreads();
        prefix |= (s_sel << shift);
        kneed = s_kkn;
    }
    const unsigned thr_key = prefix;
    const unsigned r = kneed;
    const float m    = key2f(maxkey);
    const float thrf = key2f(thr_key);

    float lsum = 0.f; unsigned leq = 0;
    for (int i = tid; i < LSEQ; i += 256) {
        unsigned key = keys[i];
        if (key > thr_key)       lsum += __expf(key2f(key) - m);
        else if (key == thr_key) leq++;
    }
#pragma unroll
    for (int off = 16; off > 0; off >>= 1) {
        lsum += __shfl_xor_sync(0xffffffffu, lsum, off);
        leq  += __shfl_xor_sync(0xffffffffu, leq,  off);
    }
    if (lane == 0) { warp_f[wid] = lsum; warp_u[wid] = leq; }
    __syncthreads();
    if (tid == 0) {
        float fs = 0.f; unsigned ue = 0;
#pragma unroll
        for (int w = 0; w < 8; w++) { fs += warp_f[w]; ue += warp_u[w]; }
        s_sum = fs; s_eq = ue;
    }
    __syncthreads();

    const float eth   = __expf(thrf - m);
    const float denom = s_sum + (float)r * eth;
    const float inv   = 1.0f / denom;
    const float peq   = eth * inv;
    const bool  fast  = (s_eq == r);

    for (int i = tid; i < LSEQ; i += 256) {
        unsigned key = keys[i];
        float p = 0.f;
        if (key > thr_key)               p = __expf(key2f(key) - m) * inv;
        else if (key == thr_key && fast) p = peq;
        srow[i] = p;
    }
    if (!fast) {
        __syncthreads();
        if (tid == 0) {
            unsigned cnt = 0;
            for (int i = 0; i < LSEQ; i++) {
                if (keys[i] == thr_key) {
                    if (cnt < r) srow[i] = peq;
                    cnt++;
                }
            }
        }
    }
}

// ============================================================
// ctx = P @ V per (b,h) (fp32 SIMT, unchanged)
// ============================================================
__global__ __launch_bounds__(256) void attnv_kernel()
{
    __shared__ __align__(16) float Ps[2][8][256];
    __shared__ __align__(16) float Vs[2][8][64];
    const int tid = threadIdx.x;
    const int tx = tid & 7, ty = tid >> 3;
    const int pm = tid >> 1;
    const int pc = (tid & 1) * 4;
    const int vr = tid >> 4;
    const int vc = (tid & 15) * 4;
    const int bh = blockIdx.z, b = bh >> 4, h = bh & 15;
    const int m0 = blockIdx.x * 256;

    const float* Sb = g_S + (size_t)bh * LSEQ * LSEQ;
    const float* Pb = Sb + (size_t)m0 * LSEQ;
    const float* Vb = g_V + (size_t)b * LSEQ * DMODEL + h * DKH;

    {
        float4 p0 = *(const float4*)(Pb + (size_t)pm * LSEQ + pc);
        float4 p1 = *(const float4*)(Pb + (size_t)(pm + 128) * LSEQ + pc);
        Ps[0][pc + 0][pm] = p0.x; Ps[0][pc + 1][pm] = p0.y;
        Ps[0][pc + 2][pm] = p0.z; Ps[0][pc + 3][pm] = p0.w;
        Ps[0][pc + 0][pm + 128] = p1.x; Ps[0][pc + 1][pm + 128] = p1.y;
        Ps[0][pc + 2][pm + 128] = p1.z; Ps[0][pc + 3][pm + 128] = p1.w;
        if (tid < 128) {
            float4 vv = *(const float4*)(Vb + (size_t)vr * DMODEL + vc);
            *(float4*)&Vs[0][vr][vc] = vv;
        }
    }
    __syncthreads();

    float acc[8][8] = {};
    int rb = 0;
    for (int k0 = 0; k0 < LSEQ; k0 += 8) {
        const bool nxt = (k0 + 8) < LSEQ;
        float4 p0n, p1n, vn;
        if (nxt) {
            p0n = *(const float4*)(Pb + (size_t)pm * LSEQ + k0 + 8 + pc);
            p1n = *(const float4*)(Pb + (size_t)(pm + 128) * LSEQ + k0 + 8 + pc);
            if (tid < 128)
                vn = *(const float4*)(Vb + (size_t)(k0 + 8 + vr) * DMODEL + vc);
        }
#pragma unroll
        for (int kk = 0; kk < 8; kk++) {
            float4 a0 = *(const float4*)&Ps[rb][kk][ty * 8];
            float4 a1 = *(const float4*)&Ps[rb][kk][ty * 8 + 4];
            float4 b0 = *(const float4*)&Vs[rb][kk][tx * 8];
            float4 b1 = *(const float4*)&Vs[rb][kk][tx * 8 + 4];
            float a8[8] = {a0.x, a0.y, a0.z, a0.w, a1.x, a1.y, a1.z, a1.w};
            float b8[8] = {b0.x, b0.y, b0.z, b0.w, b1.x, b1.y, b1.z, b1.w};
#pragma unroll
            for (int i = 0; i < 8; i++)
#pragma unroll
                for (int j = 0; j < 8; j++)
                    acc[i][j] += a8[i] * b8[j];
        }
        if (nxt) {
            const int wb2 = rb ^ 1;
            Ps[wb2][pc + 0][pm] = p0n.x; Ps[wb2][pc + 1][pm] = p0n.y;
            Ps[wb2][pc + 2][pm] = p0n.z; Ps[wb2][pc + 3][pm] = p0n.w;
            Ps[wb2][pc + 0][pm + 128] = p1n.x; Ps[wb2][pc + 1][pm + 128] = p1n.y;
            Ps[wb2][pc + 2][pm + 128] = p1n.z; Ps[wb2][pc + 3][pm + 128] = p1n.w;
            if (tid < 128)
                *(float4*)&Vs[wb2][vr][vc] = vn;
            __syncthreads();
            rb = wb2;
        }
    }
    float* Cb = g_ctx + (size_t)b * LSEQ * DMODEL + h * DKH;
#pragma unroll
    for (int i = 0; i < 8; i++) {
        float* cr = Cb + (size_t)(m0 + ty * 8 + i) * DMODEL + tx * 8;
        float4 o0 = {acc[i][0], acc[i][1], acc[i][2], acc[i][3]};
        float4 o1 = {acc[i][4], acc[i][5], acc[i][6], acc[i][7]};
        *(float4*)cr = o0; *(float4*)(cr + 4) = o1;
    }
}

// ============================================================
extern "C" void kernel_launch(void* const* d_in, const int* in_sizes, int n_in,
                              void* d_out, int out_size)
{
    const float* q  = (const float*)d_in[0];
    const float* k  = (const float*)d_in[1];
    const float* v  = (const float*)d_in[2];
    const float* Wq = (const float*)d_in[3];
    const float* bq = (const float*)d_in[4];
    const float* Wk = (const float*)d_in[5];
    const float* bk = (const float*)d_in[6];
    const float* Wv = (const float*)d_in[7];
    const float* bv = (const float*)d_in[8];
    const float* Wo = (const float*)d_in[9];
    const float* bo = (const float*)d_in[10];
    float* out = (float*)d_out;

    static float *gQ = nullptr, *gK = nullptr, *gV = nullptr, *gC = nullptr;
    static __half *gA = nullptr, *gB = nullptr;
    if (!gQ) {
        cudaGetSymbolAddress((void**)&gQ, g_Q);
        cudaGetSymbolAddress((void**)&gK, g_K);
        cudaGetSymbolAddress((void**)&gV, g_V);
        cudaGetSymbolAddress((void**)&gC, g_ctx);
        cudaGetSymbolAddress((void**)&gA, g_Asp);
        cudaGetSymbolAddress((void**)&gB, g_Bsp);
    }

    dim3 blk(256);
    const int NX = BLM * DMODEL;       // activation elements
    const int NW = DMODEL * DMODEL;    // weight elements
    dim3 gsx((NX + 255) / 256), gsw((NW + 255) / 256);
    dim3 gmm(DMODEL / 64, BLM / 128);  // (16, 32)

    // Q projection
    split_x_kernel<<<gsx, blk>>>(q, gA, NX);
    split_w_kernel<<<gsw, blk>>>(Wq, gB, NW);
    mm_wmma_kernel<<<gmm, blk>>>(gA, gB, bq, gQ);
    // K projection
    split_x_kernel<<<gsx, blk>>>(k, gA, NX);
    split_w_kernel<<<gsw, blk>>>(Wk, gB, NW);
    mm_wmma_kernel<<<gmm, blk>>>(gA, gB, bk, gK);
    // V projection
    split_x_kernel<<<gsx, blk>>>(v, gA, NX);
    split_w_kernel<<<gsw, blk>>>(Wv, gB, NW);
    mm_wmma_kernel<<<gmm, blk>>>(gA, gB, bv, gV);

    dim3 gsc(LSEQ / 128, LSEQ / 128, BHN);        // (16, 16, 32)
    scores_kernel<<<gsc, blk>>>();

    topk_softmax_kernel<<<BHN * LSEQ, blk>>>();   // 65536 blocks

    dim3 gav(LSEQ / 256, 1, BHN);                 // (8, 1, 32)
    attnv_kernel<<<gav, blk>>>();

    // Output projection
    split_x_kernel<<<gsx, blk>>>(gC, gA, NX);
    split_w_kernel<<<gsw, blk>>>(Wo, gB, NW);
    mm_wmma_kernel<<<gmm, blk>>>(gA, gB, bo, out);
}

// round 10
// speedup vs baseline: 1.7541x; 1.2391x over previous
#include <cuda_runtime.h>
#include <cuda_fp16.h>
#include <mma.h>

using namespace nvcuda;

#define BATCH   2
#define LSEQ    2048
#define DMODEL  1024
#define NHEADS  16
#define DKH     64
#define BHN     (BATCH * NHEADS)     // 32
#define BLM     (BATCH * LSEQ)       // 4096
#define TOPK    (LSEQ / 2)           // 1024
#define KSPLIT  3072                 // fp16x3 K-concat length
#define WSCALE  64.0f                // weight pre-scale (keeps W low-part normal)
#define PSCALE  1024.0f              // prob pre-scale in attnv

// ---- scratch (static device arrays; allocation-free per harness rules) ----
__device__ float g_Q[(size_t)BLM * DMODEL];
__device__ float g_K[(size_t)BLM * DMODEL];
__device__ float g_V[(size_t)BLM * DMODEL];
__device__ float g_ctx[(size_t)BLM * DMODEL];
__device__ float g_S[(size_t)BHN * LSEQ * LSEQ];   // 537 MB scores/probs
__device__ __half g_Asp[(size_t)BLM * KSPLIT];     // 24 MB split activations
__device__ __half g_Bsp[(size_t)DMODEL * KSPLIT];  //  6 MB split weights

// monotone float<->uint mapping (order-preserving)
__device__ __forceinline__ unsigned f2key(float f) {
    unsigned u = __float_as_uint(f);
    return (u & 0x80000000u) ? ~u : (u | 0x80000000u);
}
__device__ __forceinline__ float key2f(unsigned key) {
    unsigned u = (key & 0x80000000u) ? (key ^ 0x80000000u) : ~key;
    return __uint_as_float(u);
}

// ============================================================
// fp16x3 split kernels (Dekker 2-way split, drop al*bl term):
// X row -> [ah | ah | al], W row (pre-scaled by WSCALE) -> [bh | bl | bh]
// ============================================================
__global__ __launch_bounds__(256) void split_x_kernel(
    const float* __restrict__ X, __half* __restrict__ O, int nelem)
{
    int i = blockIdx.x * 256 + threadIdx.x;
    if (i >= nelem) return;
    int r = i >> 10, c = i & 1023;
    float a = X[i];
    __half ah = __float2half(a);
    __half al = __float2half(a - __half2float(ah));
    __half* o = O + (size_t)r * KSPLIT;
    o[c] = ah; o[1024 + c] = ah; o[2048 + c] = al;
}
__global__ __launch_bounds__(256) void split_w_kernel(
    const float* __restrict__ W, __half* __restrict__ O, int nelem)
{
    int i = blockIdx.x * 256 + threadIdx.x;
    if (i >= nelem) return;
    int r = i >> 10, c = i & 1023;
    float b = W[i] * WSCALE;
    __half bh = __float2half(b);
    __half bl = __float2half(b - __half2float(bh));
    __half* o = O + (size_t)r * KSPLIT;
    o[c] = bh; o[1024 + c] = bl; o[2048 + c] = bh;
}

// ============================================================
// WMMA projection GEMM: Y = (X @ (WSCALE*W)^T)/WSCALE + bias
// CTA tile 128x64, 8 warps (4x2), warp 32x32 via 2x2 wmma.
// ============================================================
#define AST 40
__global__ __launch_bounds__(256) void mm_wmma_kernel(
    const __half* __restrict__ A,   // [BLM][KSPLIT]
    const __half* __restrict__ Bm,  // [DMODEL][KSPLIT] (scaled)
    const float* __restrict__ bias, float* __restrict__ Y)
{
    __shared__ __align__(16) __half As[2][128][AST];
    __shared__ __align__(16) __half Bs[2][64][AST];
    __shared__ __align__(16) float BiasS[16][72];

    const int tid = threadIdx.x;
    const int wid = tid >> 5;
    const int wr = wid >> 1;
    const int wc = wid & 1;
    const int m0 = blockIdx.y * 128, n0 = blockIdx.x * 64;

    for (int i = tid; i < 16 * 64; i += 256) {
        int r = i >> 6, c = i & 63;
        BiasS[r][c] = bias[n0 + c] * WSCALE;
    }

    const int ar = tid >> 2;
    const int au = tid & 3;
    const int br = tid >> 2;
    const __half* Ab = A + (size_t)m0 * KSPLIT;
    const __half* Bb = Bm + (size_t)n0 * KSPLIT;

    {
        uint4 a0 = *(const uint4*)(Ab + (size_t)ar * KSPLIT + au * 8);
        uint4 a1 = *(const uint4*)(Ab + (size_t)(ar + 64) * KSPLIT + au * 8);
        uint4 b0 = *(const uint4*)(Bb + (size_t)br * KSPLIT + au * 8);
        *(uint4*)&As[0][ar][au * 8] = a0;
        *(uint4*)&As[0][ar + 64][au * 8] = a1;
        *(uint4*)&Bs[0][br][au * 8] = b0;
    }
    __syncthreads();

    wmma::fragment<wmma::accumulator, 16, 16, 16, float> acc[2][2];
#pragma unroll
    for (int i = 0; i < 2; i++)
#pragma unroll
        for (int j = 0; j < 2; j++)
            wmma::load_matrix_sync(acc[i][j], &BiasS[0][wc * 32 + j * 16], 72,
                                   wmma::mem_row_major);

    const int NST = KSPLIT / 32;       // 96 stages
    for (int s = 0; s < NST; s++) {
        const int buf = s & 1;
        uint4 pa0, pa1, pb0;
        const bool nxt = (s + 1) < NST;
        if (nxt) {
            int ko = (s + 1) * 32 + au * 8;
            pa0 = *(const uint4*)(Ab + (size_t)ar * KSPLIT + ko);
            pa1 = *(const uint4*)(Ab + (size_t)(ar + 64) * KSPLIT + ko);
            pb0 = *(const uint4*)(Bb + (size_t)br * KSPLIT + ko);
        }
#pragma unroll
        for (int kk = 0; kk < 32; kk += 16) {
            wmma::fragment<wmma::matrix_a, 16, 16, 16, __half, wmma::row_major> af[2];
            wmma::fragment<wmma::matrix_b, 16, 16, 16, __half, wmma::col_major> bf[2];
            wmma::load_matrix_sync(af[0], &As[buf][wr * 32][kk], AST);
            wmma::load_matrix_sync(af[1], &As[buf][wr * 32 + 16][kk], AST);
            wmma::load_matrix_sync(bf[0], &Bs[buf][wc * 32][kk], AST);
            wmma::load_matrix_sync(bf[1], &Bs[buf][wc * 32 + 16][kk], AST);
#pragma unroll
            for (int i = 0; i < 2; i++)
#pragma unroll
                for (int j = 0; j < 2; j++)
                    wmma::mma_sync(acc[i][j], af[i], bf[j], acc[i][j]);
        }
        if (nxt) {
            const int nb = buf ^ 1;
            *(uint4*)&As[nb][ar][au * 8] = pa0;
            *(uint4*)&As[nb][ar + 64][au * 8] = pa1;
            *(uint4*)&Bs[nb][br][au * 8] = pb0;
            __syncthreads();
        }
    }

    const float inv = 1.0f / WSCALE;
#pragma unroll
    for (int i = 0; i < 2; i++)
#pragma unroll
        for (int j = 0; j < 2; j++) {
#pragma unroll
            for (int e = 0; e < acc[i][j].num_elements; e++)
                acc[i][j].x[e] *= inv;
            wmma::store_matrix_sync(
                Y + (size_t)(m0 + wr * 32 + i * 16) * DMODEL + n0 + wc * 32 + j * 16,
                acc[i][j], DMODEL, wmma::mem_row_major);
        }
}

// ============================================================
// Scores (wmma, inline fp16x3): S[bh][q][k] = (Q . K) / 8
// CTA 128x128 output, 8 warps (2x4), warp 64x32, d_k in 2 chunks of 32.
// ============================================================
__global__ __launch_bounds__(256) void scores_wmma_kernel()
{
    __shared__ __align__(16) __half Qh[128][40], Ql[128][40];
    __shared__ __align__(16) __half Kh[128][40], Kl[128][40];
    const int tid = threadIdx.x;
    const int wid = tid >> 5;
    const int wr = wid >> 2;           // 0..1 -> rows wr*64
    const int wc = wid & 3;            // 0..3 -> cols wc*32
    const int bh = blockIdx.z, b = bh >> 4, h = bh & 15;
    const int q0 = blockIdx.y * 128, k0 = blockIdx.x * 128;
    const float* Qb = g_Q + (size_t)(b * LSEQ + q0) * DMODEL + h * DKH;
    const float* Kb = g_K + (size_t)(b * LSEQ + k0) * DMODEL + h * DKH;

    wmma::fragment<wmma::accumulator, 16, 16, 16, float> acc[4][2];
#pragma unroll
    for (int i = 0; i < 4; i++)
#pragma unroll
        for (int j = 0; j < 2; j++)
            wmma::fill_fragment(acc[i][j], 0.0f);

    for (int kc = 0; kc < DKH; kc += 32) {
        // load+split 128x32 of Q and K: 1024 float4 each -> 4/thread
#pragma unroll
        for (int it = 0; it < 4; it++) {
            int f = tid + 256 * it;
            int r = f >> 3, c4 = (f & 7) * 4;
            float4 qv = *(const float4*)(Qb + (size_t)r * DMODEL + kc + c4);
            float4 kv = *(const float4*)(Kb + (size_t)r * DMODEL + kc + c4);
            float qa[4] = {qv.x, qv.y, qv.z, qv.w};
            float ka[4] = {kv.x, kv.y, kv.z, kv.w};
#pragma unroll
            for (int e = 0; e < 4; e++) {
                __half qh = __float2half(qa[e]);
                Qh[r][c4 + e] = qh;
                Ql[r][c4 + e] = __float2half(qa[e] - __half2float(qh));
                __half kh = __float2half(ka[e]);
                Kh[r][c4 + e] = kh;
                Kl[r][c4 + e] = __float2half(ka[e] - __half2float(kh));
            }
        }
        __syncthreads();
#pragma unroll
        for (int kk = 0; kk < 32; kk += 16) {
            wmma::fragment<wmma::matrix_b, 16, 16, 16, __half, wmma::col_major> bh_f[2], bl_f[2];
#pragma unroll
            for (int j = 0; j < 2; j++) {
                wmma::load_matrix_sync(bh_f[j], &Kh[wc * 32 + j * 16][kk], 40);
                wmma::load_matrix_sync(bl_f[j], &Kl[wc * 32 + j * 16][kk], 40);
            }
#pragma unroll
            for (int i = 0; i < 4; i++) {
                wmma::fragment<wmma::matrix_a, 16, 16, 16, __half, wmma::row_major> ah_f, al_f;
                wmma::load_matrix_sync(ah_f, &Qh[wr * 64 + i * 16][kk], 40);
                wmma::load_matrix_sync(al_f, &Ql[wr * 64 + i * 16][kk], 40);
#pragma unroll
                for (int j = 0; j < 2; j++) {
                    wmma::mma_sync(acc[i][j], ah_f, bh_f[j], acc[i][j]);
                    wmma::mma_sync(acc[i][j], ah_f, bl_f[j], acc[i][j]);
                    wmma::mma_sync(acc[i][j], al_f, bh_f[j], acc[i][j]);
                }
            }
        }
        __syncthreads();
    }
    float* Sb = g_S + (size_t)bh * LSEQ * LSEQ;
#pragma unroll
    for (int i = 0; i < 4; i++)
#pragma unroll
        for (int j = 0; j < 2; j++) {
#pragma unroll
            for (int e = 0; e < acc[i][j].num_elements; e++)
                acc[i][j].x[e] *= 0.125f;
            wmma::store_matrix_sync(
                Sb + (size_t)(q0 + wr * 64 + i * 16) * LSEQ + k0 + wc * 32 + j * 16,
                acc[i][j], LSEQ, wmma::mem_row_major);
        }
}

// ============================================================
// Per-row top-k threshold (radix select) + softmax (unchanged)
// ============================================================
__global__ __launch_bounds__(256) void topk_softmax_kernel()
{
    __shared__ unsigned keys[LSEQ];
    __shared__ unsigned hist[256];
    __shared__ unsigned warp_u[8];
    __shared__ float    warp_f[8];
    __shared__ unsigned s_sel, s_kkn, s_max, s_eq;
    __shared__ float    s_sum;

    const int tid  = threadIdx.x;
    const int lane = tid & 31, wid = tid >> 5;
    float* __restrict__ srow = g_S + (size_t)blockIdx.x * LSEQ;

    unsigned lmax = 0;
    for (int i = tid; i < LSEQ; i += 256) {
        unsigned key = f2key(srow[i]);
        keys[i] = key;
        lmax = key > lmax ? key : lmax;
    }
#pragma unroll
    for (int off = 16; off > 0; off >>= 1) {
        unsigned o = __shfl_xor_sync(0xffffffffu, lmax, off);
        lmax = o > lmax ? o : lmax;
    }
    if (lane == 0) warp_u[wid] = lmax;
    __syncthreads();
    if (tid == 0) {
        unsigned m = warp_u[0];
#pragma unroll
        for (int w = 1; w < 8; w++) m = warp_u[w] > m ? warp_u[w] : m;
        s_max = m;
    }
    __syncthreads();
    const unsigned maxkey = s_max;

    unsigned prefix = 0;
    unsigned kneed  = TOPK;
    for (int shift = 24; shift >= 0; shift -= 8) {
        hist[tid] = 0;
        __syncthreads();
        unsigned mask_hi = (shift == 24) ? 0u : (0xFFFFFFFFu << (shift + 8));
        for (int i = tid; i < LSEQ; i += 256) {
            unsigned key = keys[i];
            if ((key & mask_hi) == prefix)
                atomicAdd(&hist[(key >> shift) & 0xFFu], 1u);
        }
        __syncthreads();
        const unsigned h = hist[tid];
        unsigned v = h;
#pragma unroll
        for (int off = 1; off < 32; off <<= 1) {
            unsigned t = __shfl_down_sync(0xffffffffu, v, off);
            if (lane + off < 32) v += t;
        }
        if (lane == 0) warp_u[wid] = v;
        __syncthreads();
        unsigned wtail = 0;
#pragma unroll
        for (int w = 0; w < 8; w++) if (w > wid) wtail += warp_u[w];
        const unsigned sufi = v + wtail;
        const unsigned sufn = sufi - h;
        if (sufi >= kneed && sufn < kneed) {
            s_sel = (unsigned)tid;
            s_kkn = kneed - sufn;
        }
        __syncthreads();
        prefix |= (s_sel << shift);
        kneed = s_kkn;
    }
    const unsigned thr_key = prefix;
    const unsigned r = kneed;
    const float m    = key2f(maxkey);
    const float thrf = key2f(thr_key);

    float lsum = 0.f; unsigned leq = 0;
    for (int i = tid; i < LSEQ; i += 256) {
        unsigned key = keys[i];
        if (key > thr_key)       lsum += __expf(key2f(key) - m);
        else if (key == thr_key) leq++;
    }
#pragma unroll
    for (int off = 16; off > 0; off >>= 1) {
        lsum += __shfl_xor_sync(0xffffffffu, lsum, off);
        leq  += __shfl_xor_sync(0xffffffffu, leq,  off);
    }
    if (lane == 0) { warp_f[wid] = lsum; warp_u[wid] = leq; }
    __syncthreads();
    if (tid == 0) {
        float fs = 0.f; unsigned ue = 0;
#pragma unroll
        for (int w = 0; w < 8; w++) { fs += warp_f[w]; ue += warp_u[w]; }
        s_sum = fs; s_eq = ue;
    }
    __syncthreads();

    const float eth   = __expf(thrf - m);
    const float denom = s_sum + (float)r * eth;
    const float inv   = 1.0f / denom;
    const float peq   = eth * inv;
    const bool  fast  = (s_eq == r);

    for (int i = tid; i < LSEQ; i += 256) {
        unsigned key = keys[i];
        float p = 0.f;
        if (key > thr_key)               p = __expf(key2f(key) - m) * inv;
        else if (key == thr_key && fast) p = peq;
        srow[i] = p;
    }
    if (!fast) {
        __syncthreads();
        if (tid == 0) {
            unsigned cnt = 0;
            for (int i = 0; i < LSEQ; i++) {
                if (keys[i] == thr_key) {
                    if (cnt < r) srow[i] = peq;
                    cnt++;
                }
            }
        }
    }
}

// ============================================================
// attnv (wmma, inline fp16x3): ctx = P @ V per (b,h)
// CTA 128 rows x 64 cols (full d_k), 8 warps (4x2), warp 32x32.
// P scaled x1024 before split (keeps low part normal); /1024 at epilogue.
// ============================================================
__global__ __launch_bounds__(256) void attnv_wmma_kernel()
{
    __shared__ __align__(16) __half Ph[128][40], Pl[128][40];
    __shared__ __align__(16) __half Vh[32][72], Vl[32][72];
    const int tid = threadIdx.x;
    const int wid = tid >> 5;
    const int wr = wid >> 1;           // 0..3 -> rows wr*32
    const int wc = wid & 1;            // 0..1 -> cols wc*32
    const int bh = blockIdx.z, b = bh >> 4, h = bh & 15;
    const int m0 = blockIdx.x * 128;

    const float* Pb = g_S + (size_t)bh * LSEQ * LSEQ + (size_t)m0 * LSEQ;
    const float* Vb = g_V + (size_t)b * LSEQ * DMODEL + h * DKH;

    wmma::fragment<wmma::accumulator, 16, 16, 16, float> acc[2][2];
#pragma unroll
    for (int i = 0; i < 2; i++)
#pragma unroll
        for (int j = 0; j < 2; j++)
            wmma::fill_fragment(acc[i][j], 0.0f);

    for (int k0 = 0; k0 < LSEQ; k0 += 32) {
        // P tile 128x32: 1024 float4 -> 4/thread; scale x1024, split
#pragma unroll
        for (int it = 0; it < 4; it++) {
            int f = tid + 256 * it;
            int r = f >> 3, c4 = (f & 7) * 4;
            float4 pv = *(const float4*)(Pb + (size_t)r * LSEQ + k0 + c4);
            float pa[4] = {pv.x * PSCALE, pv.y * PSCALE, pv.z * PSCALE, pv.w * PSCALE};
#pragma unroll
            for (int e = 0; e < 4; e++) {
                __half ph = __float2half(pa[e]);
                Ph[r][c4 + e] = ph;
                Pl[r][c4 + e] = __float2half(pa[e] - __half2float(ph));
            }
        }
        // V tile 32x64: 512 float4 -> 2/thread
#pragma unroll
        for (int it = 0; it < 2; it++) {
            int f = tid + 256 * it;
            int r = f >> 4, c4 = (f & 15) * 4;
            float4 vv = *(const float4*)(Vb + (size_t)(k0 + r) * DMODEL + c4);
            float va[4] = {vv.x, vv.y, vv.z, vv.w};
#pragma unroll
            for (int e = 0; e < 4; e++) {
                __half vh = __float2half(va[e]);
                Vh[r][c4 + e] = vh;
                Vl[r][c4 + e] = __float2half(va[e] - __half2float(vh));
            }
        }
        __syncthreads();
#pragma unroll
        for (int kk = 0; kk < 32; kk += 16) {
            wmma::fragment<wmma::matrix_b, 16, 16, 16, __half, wmma::row_major> bh_f[2], bl_f[2];
#pragma unroll
            for (int j = 0; j < 2; j++) {
                wmma::load_matrix_sync(bh_f[j], &Vh[kk][wc * 32 + j * 16], 72);
                wmma::load_matrix_sync(bl_f[j], &Vl[kk][wc * 32 + j * 16], 72);
            }
#pragma unroll
            for (int i = 0; i < 2; i++) {
                wmma::fragment<wmma::matrix_a, 16, 16, 16, __half, wmma::row_major> ah_f, al_f;
                wmma::load_matrix_sync(ah_f, &Ph[wr * 32 + i * 16][kk], 40);
                wmma::load_matrix_sync(al_f, &Pl[wr * 32 + i * 16][kk], 40);
#pragma unroll
                for (int j = 0; j < 2; j++) {
                    wmma::mma_sync(acc[i][j], ah_f, bh_f[j], acc[i][j]);
                    wmma::mma_sync(acc[i][j], ah_f, bl_f[j], acc[i][j]);
                    wmma::mma_sync(acc[i][j], al_f, bh_f[j], acc[i][j]);
                }
            }
        }
        __syncthreads();
    }
    float* Cb = g_ctx + (size_t)(b * LSEQ + m0) * DMODEL + h * DKH;
    const float inv = 1.0f / PSCALE;
#pragma unroll
    for (int i = 0; i < 2; i++)
#pragma unroll
        for (int j = 0; j < 2; j++) {
#pragma unroll
            for (int e = 0; e < acc[i][j].num_elements; e++)
                acc[i][j].x[e] *= inv;
            wmma::store_matrix_sync(
                Cb + (size_t)(wr * 32 + i * 16) * DMODEL + wc * 32 + j * 16,
                acc[i][j], DMODEL, wmma::mem_row_major);
        }
}

// ============================================================
extern "C" void kernel_launch(void* const* d_in, const int* in_sizes, int n_in,
                              void* d_out, int out_size)
{
    const float* q  = (const float*)d_in[0];
    const float* k  = (const float*)d_in[1];
    const float* v  = (const float*)d_in[2];
    const float* Wq = (const float*)d_in[3];
    const float* bq = (const float*)d_in[4];
    const float* Wk = (const float*)d_in[5];
    const float* bk = (const float*)d_in[6];
    const float* Wv = (const float*)d_in[7];
    const float* bv = (const float*)d_in[8];
    const float* Wo = (const float*)d_in[9];
    const float* bo = (const float*)d_in[10];
    float* out = (float*)d_out;

    static float *gQ = nullptr, *gK = nullptr, *gV = nullptr, *gC = nullptr;
    static __half *gA = nullptr, *gB = nullptr;
    if (!gQ) {
        cudaGetSymbolAddress((void**)&gQ, g_Q);
        cudaGetSymbolAddress((void**)&gK, g_K);
        cudaGetSymbolAddress((void**)&gV, g_V);
        cudaGetSymbolAddress((void**)&gC, g_ctx);
        cudaGetSymbolAddress((void**)&gA, g_Asp);
        cudaGetSymbolAddress((void**)&gB, g_Bsp);
    }

    dim3 blk(256);
    const int NX = BLM * DMODEL;
    const int NW = DMODEL * DMODEL;
    dim3 gsx((NX + 255) / 256), gsw((NW + 255) / 256);
    dim3 gmm(DMODEL / 64, BLM / 128);  // (16, 32)

    // Q projection
    split_x_kernel<<<gsx, blk>>>(q, gA, NX);
    split_w_kernel<<<gsw, blk>>>(Wq, gB, NW);
    mm_wmma_kernel<<<gmm, blk>>>(gA, gB, bq, gQ);
    // K projection
    split_x_kernel<<<gsx, blk>>>(k, gA, NX);
    split_w_kernel<<<gsw, blk>>>(Wk, gB, NW);
    mm_wmma_kernel<<<gmm, blk>>>(gA, gB, bk, gK);
    // V projection
    split_x_kernel<<<gsx, blk>>>(v, gA, NX);
    split_w_kernel<<<gsw, blk>>>(Wv, gB, NW);
    mm_wmma_kernel<<<gmm, blk>>>(gA, gB, bv, gV);

    dim3 gsc(LSEQ / 128, LSEQ / 128, BHN);        // (16, 16, 32)
    scores_wmma_kernel<<<gsc, blk>>>();

    topk_softmax_kernel<<<BHN * LSEQ, blk>>>();   // 65536 blocks

    dim3 gav(LSEQ / 128, 1, BHN);                 // (16, 1, 32)
    attnv_wmma_kernel<<<gav, blk>>>();

    // Output projection
    split_x_kernel<<<gsx, blk>>>(gC, gA, NX);
    split_w_kernel<<<gsw, blk>>>(Wo, gB, NW);
    mm_wmma_kernel<<<gmm, blk>>>(gA, gB, bo, out);
}

// round 14
// speedup vs baseline: 1.8496x; 1.0544x over previous
#include <cuda_runtime.h>
#include <cuda_fp16.h>
#include <mma.h>

using namespace nvcuda;

#define BATCH   2
#define LSEQ    2048
#define DMODEL  1024
#define NHEADS  16
#define DKH     64
#define BHN     (BATCH * NHEADS)     // 32
#define BLM     (BATCH * LSEQ)       // 4096
#define TOPK    (LSEQ / 2)           // 1024
#define KSPLIT  3072                 // fp16x3 K-concat length
#define WSCALE  64.0f                // weight pre-scale (keeps W low-part normal)
#define PSCALE  1024.0f              // prob pre-scale in attnv

// ---- scratch (static device arrays; allocation-free per harness rules) ----
__device__ float g_Q[(size_t)BLM * DMODEL];
__device__ float g_K[(size_t)BLM * DMODEL];
__device__ float g_V[(size_t)BLM * DMODEL];
__device__ float g_ctx[(size_t)BLM * DMODEL];
__device__ float g_S[(size_t)BHN * LSEQ * LSEQ];   // 537 MB scores
__device__ float4 g_rp[(size_t)BHN * LSEQ];        // per-row softmax params
__device__ __half g_Asp[(size_t)BLM * KSPLIT];     // 24 MB split activations
__device__ __half g_Bsp[(size_t)DMODEL * KSPLIT];  //  6 MB split weights

// monotone float<->uint mapping (order-preserving)
__device__ __forceinline__ unsigned f2key(float f) {
    unsigned u = __float_as_uint(f);
    return (u & 0x80000000u) ? ~u : (u | 0x80000000u);
}
__device__ __forceinline__ float key2f(unsigned key) {
    unsigned u = (key & 0x80000000u) ? (key ^ 0x80000000u) : ~key;
    return __uint_as_float(u);
}

// ============================================================
// fp16x3 split kernels (Dekker 2-way split, drop al*bl term)
// ============================================================
__global__ __launch_bounds__(256) void split_x_kernel(
    const float* __restrict__ X, __half* __restrict__ O, int nelem)
{
    int i = blockIdx.x * 256 + threadIdx.x;
    if (i >= nelem) return;
    int r = i >> 10, c = i & 1023;
    float a = X[i];
    __half ah = __float2half(a);
    __half al = __float2half(a - __half2float(ah));
    __half* o = O + (size_t)r * KSPLIT;
    o[c] = ah; o[1024 + c] = ah; o[2048 + c] = al;
}
__global__ __launch_bounds__(256) void split_w_kernel(
    const float* __restrict__ W, __half* __restrict__ O, int nelem)
{
    int i = blockIdx.x * 256 + threadIdx.x;
    if (i >= nelem) return;
    int r = i >> 10, c = i & 1023;
    float b = W[i] * WSCALE;
    __half bh = __float2half(b);
    __half bl = __float2half(b - __half2float(bh));
    __half* o = O + (size_t)r * KSPLIT;
    o[c] = bh; o[1024 + c] = bl; o[2048 + c] = bh;
}

// ============================================================
// WMMA projection GEMM: Y = (X @ (WSCALE*W)^T)/WSCALE + bias
// CTA tile 128x128, 8 warps (2x4), warp 64x32 via 4x2 wmma frags.
// BK=16 double-buffered (24.6 KB); separate bias smem (no aliasing).
// Per-acc mma chain is the same ascending K=16 sequence as before.
// ============================================================
#define MST 24
__global__ __launch_bounds__(256) void mm_wmma_kernel(
    const __half* __restrict__ A,   // [BLM][KSPLIT]
    const __half* __restrict__ Bm,  // [DMODEL][KSPLIT] (scaled)
    const float* __restrict__ bias, float* __restrict__ Y)
{
    __shared__ __align__(16) __half As[2][128][MST];   // 12288 B
    __shared__ __align__(16) __half Bs[2][128][MST];   // 12288 B
    __shared__ __align__(16) float BiasS[16][136];     //  8704 B

    const int tid = threadIdx.x;
    const int wid = tid >> 5;
    const int wr = wid >> 2;           // 0..1 -> rows wr*64
    const int wc = wid & 3;            // 0..3 -> cols wc*32
    const int m0 = blockIdx.y * 128, n0 = blockIdx.x * 128;

    // bias tile (16 identical rows x 128 cols)
    for (int i = tid; i < 16 * 128; i += 256) {
        int r = i >> 7, c = i & 127;
        BiasS[r][c] = bias[n0 + c];
    }

    const int lr = tid >> 1;           // 0..127
    const int lu = (tid & 1) * 8;      // half-offset 0 or 8 (1x uint4)
    const __half* Ab = A + (size_t)(m0 + lr) * KSPLIT + lu;
    const __half* Bb = Bm + (size_t)(n0 + lr) * KSPLIT + lu;

    // prologue: stage 0
    {
        uint4 a0 = *(const uint4*)(Ab);
        uint4 b0 = *(const uint4*)(Bb);
        *(uint4*)&As[0][lr][lu] = a0;
        *(uint4*)&Bs[0][lr][lu] = b0;
    }
    __syncthreads();

    wmma::fragment<wmma::accumulator, 16, 16, 16, float> acc[4][2];
#pragma unroll
    for (int i = 0; i < 4; i++)
#pragma unroll
        for (int j = 0; j < 2; j++)
            wmma::fill_fragment(acc[i][j], 0.0f);

    const int NST = KSPLIT / 16;       // 192 stages
    for (int s = 0; s < NST; s++) {
        const int buf = s & 1;
        uint4 pa0, pb0;
        const bool nxt = (s + 1) < NST;
        if (nxt) {
            int ko = (s + 1) * 16;
            pa0 = *(const uint4*)(Ab + ko);
            pb0 = *(const uint4*)(Bb + ko);
        }
        {
            wmma::fragment<wmma::matrix_b, 16, 16, 16, __half, wmma::col_major> bf[2];
#pragma unroll
            for (int j = 0; j < 2; j++)
                wmma::load_matrix_sync(bf[j], &Bs[buf][wc * 32 + j * 16][0], MST);
#pragma unroll
            for (int i = 0; i < 4; i++) {
                wmma::fragment<wmma::matrix_a, 16, 16, 16, __half, wmma::row_major> af;
                wmma::load_matrix_sync(af, &As[buf][wr * 64 + i * 16][0], MST);
#pragma unroll
                for (int j = 0; j < 2; j++)
                    wmma::mma_sync(acc[i][j], af, bf[j], acc[i][j]);
            }
        }
        if (nxt) {
            const int nb = buf ^ 1;
            *(uint4*)&As[nb][lr][lu] = pa0;
            *(uint4*)&Bs[nb][lr][lu] = pb0;
            __syncthreads();
        }
    }

    const float inv = 1.0f / WSCALE;
#pragma unroll
    for (int i = 0; i < 4; i++)
#pragma unroll
        for (int j = 0; j < 2; j++) {
            wmma::fragment<wmma::accumulator, 16, 16, 16, float> bfr;
            wmma::load_matrix_sync(bfr, &BiasS[0][wc * 32 + j * 16], 136,
                                   wmma::mem_row_major);
#pragma unroll
            for (int e = 0; e < acc[i][j].num_elements; e++)
                acc[i][j].x[e] = acc[i][j].x[e] * inv + bfr.x[e];
            wmma::store_matrix_sync(
                Y + (size_t)(m0 + wr * 64 + i * 16) * DMODEL + n0 + wc * 32 + j * 16,
                acc[i][j], DMODEL, wmma::mem_row_major);
        }
}

// ============================================================
// Scores (wmma, inline fp16x3): S[bh][q][k] = (Q . K) / 8
// ============================================================
__global__ __launch_bounds__(256) void scores_wmma_kernel()
{
    __shared__ __align__(16) __half Qh[128][40], Ql[128][40];
    __shared__ __align__(16) __half Kh[128][40], Kl[128][40];
    const int tid = threadIdx.x;
    const int wid = tid >> 5;
    const int wr = wid >> 2;
    const int wc = wid & 3;
    const int bh = blockIdx.z, b = bh >> 4, h = bh & 15;
    const int q0 = blockIdx.y * 128, k0 = blockIdx.x * 128;
    const float* Qb = g_Q + (size_t)(b * LSEQ + q0) * DMODEL + h * DKH;
    const float* Kb = g_K + (size_t)(b * LSEQ + k0) * DMODEL + h * DKH;

    wmma::fragment<wmma::accumulator, 16, 16, 16, float> acc[4][2];
#pragma unroll
    for (int i = 0; i < 4; i++)
#pragma unroll
        for (int j = 0; j < 2; j++)
            wmma::fill_fragment(acc[i][j], 0.0f);

    for (int kc = 0; kc < DKH; kc += 32) {
#pragma unroll
        for (int it = 0; it < 4; it++) {
            int f = tid + 256 * it;
            int r = f >> 3, c4 = (f & 7) * 4;
            float4 qv = *(const float4*)(Qb + (size_t)r * DMODEL + kc + c4);
            float4 kv = *(const float4*)(Kb + (size_t)r * DMODEL + kc + c4);
            float qa[4] = {qv.x, qv.y, qv.z, qv.w};
            float ka[4] = {kv.x, kv.y, kv.z, kv.w};
#pragma unroll
            for (int e = 0; e < 4; e++) {
                __half qh = __float2half(qa[e]);
                Qh[r][c4 + e] = qh;
                Ql[r][c4 + e] = __float2half(qa[e] - __half2float(qh));
                __half kh = __float2half(ka[e]);
                Kh[r][c4 + e] = kh;
                Kl[r][c4 + e] = __float2half(ka[e] - __half2float(kh));
            }
        }
        __syncthreads();
#pragma unroll
        for (int kk = 0; kk < 32; kk += 16) {
            wmma::fragment<wmma::matrix_b, 16, 16, 16, __half, wmma::col_major> bh_f[2], bl_f[2];
#pragma unroll
            for (int j = 0; j < 2; j++) {
                wmma::load_matrix_sync(bh_f[j], &Kh[wc * 32 + j * 16][kk], 40);
                wmma::load_matrix_sync(bl_f[j], &Kl[wc * 32 + j * 16][kk], 40);
            }
#pragma unroll
            for (int i = 0; i < 4; i++) {
                wmma::fragment<wmma::matrix_a, 16, 16, 16, __half, wmma::row_major> ah_f, al_f;
                wmma::load_matrix_sync(ah_f, &Qh[wr * 64 + i * 16][kk], 40);
                wmma::load_matrix_sync(al_f, &Ql[wr * 64 + i * 16][kk], 40);
#pragma unroll
                for (int j = 0; j < 2; j++) {
                    wmma::mma_sync(acc[i][j], ah_f, bh_f[j], acc[i][j]);
                    wmma::mma_sync(acc[i][j], ah_f, bl_f[j], acc[i][j]);
                    wmma::mma_sync(acc[i][j], al_f, bh_f[j], acc[i][j]);
                }
            }
        }
        __syncthreads();
    }
    float* Sb = g_S + (size_t)bh * LSEQ * LSEQ;
#pragma unroll
    for (int i = 0; i < 4; i++)
#pragma unroll
        for (int j = 0; j < 2; j++) {
#pragma unroll
            for (int e = 0; e < acc[i][j].num_elements; e++)
                acc[i][j].x[e] *= 0.125f;
            wmma::store_matrix_sync(
                Sb + (size_t)(q0 + wr * 64 + i * 16) * LSEQ + k0 + wc * 32 + j * 16,
                acc[i][j], LSEQ, wmma::mem_row_major);
        }
}

// ============================================================
// Per-row top-k threshold + softmax params. Fast path writes only
// per-row params (no 537MB prob write); rare tie path writes probs
// into S and a sentinel param (inv = -1).
// ============================================================
__global__ __launch_bounds__(256) void topk_softmax_kernel()
{
    __shared__ unsigned keys[LSEQ];
    __shared__ unsigned hist[256];
    __shared__ unsigned warp_u[8];
    __shared__ float    warp_f[8];
    __shared__ unsigned s_sel, s_kkn, s_max, s_eq;
    __shared__ float    s_sum;

    const int tid  = threadIdx.x;
    const int lane = tid & 31, wid = tid >> 5;
    float* __restrict__ srow = g_S + (size_t)blockIdx.x * LSEQ;

    unsigned lmax = 0;
    for (int i = tid; i < LSEQ; i += 256) {
        unsigned key = f2key(srow[i]);
        keys[i] = key;
        lmax = key > lmax ? key : lmax;
    }
#pragma unroll
    for (int off = 16; off > 0; off >>= 1) {
        unsigned o = __shfl_xor_sync(0xffffffffu, lmax, off);
        lmax = o > lmax ? o : lmax;
    }
    if (lane == 0) warp_u[wid] = lmax;
    __syncthreads();
    if (tid == 0) {
        unsigned m = warp_u[0];
#pragma unroll
        for (int w = 1; w < 8; w++) m = warp_u[w] > m ? warp_u[w] : m;
        s_max = m;
    }
    __syncthreads();
    const unsigned maxkey = s_max;

    unsigned prefix = 0;
    unsigned kneed  = TOPK;
    for (int shift = 24; shift >= 0; shift -= 8) {
        hist[tid] = 0;
        __syncthreads();
        unsigned mask_hi = (shift == 24) ? 0u : (0xFFFFFFFFu << (shift + 8));
        for (int i = tid; i < LSEQ; i += 256) {
            unsigned key = keys[i];
            if ((key & mask_hi) == prefix)
                atomicAdd(&hist[(key >> shift) & 0xFFu], 1u);
        }
        __syncthreads();
        const unsigned h = hist[tid];
        unsigned v = h;
#pragma unroll
        for (int off = 1; off < 32; off <<= 1) {
            unsigned t = __shfl_down_sync(0xffffffffu, v, off);
            if (lane + off < 32) v += t;
        }
        if (lane == 0) warp_u[wid] = v;
        __syncthreads();
        unsigned wtail = 0;
#pragma unroll
        for (int w = 0; w < 8; w++) if (w > wid) wtail += warp_u[w];
        const unsigned sufi = v + wtail;
        const unsigned sufn = sufi - h;
        if (sufi >= kneed && sufn < kneed) {
            s_sel = (unsigned)tid;
            s_kkn = kneed - sufn;
        }
        __syncthreads();
        prefix |= (s_sel << shift);
        kneed = s_kkn;
    }
    const unsigned thr_key = prefix;
    const unsigned r = kneed;
    const float m    = key2f(maxkey);
    const float thrf = key2f(thr_key);

    float lsum = 0.f; unsigned leq = 0;
    for (int i = tid; i < LSEQ; i += 256) {
        unsigned key = keys[i];
        if (key > thr_key)       lsum += __expf(key2f(key) - m);
        else if (key == thr_key) leq++;
    }
#pragma unroll
    for (int off = 16; off > 0; off >>= 1) {
        lsum += __shfl_xor_sync(0xffffffffu, lsum, off);
        leq  += __shfl_xor_sync(0xffffffffu, leq,  off);
    }
    if (lane == 0) { warp_f[wid] = lsum; warp_u[wid] = leq; }
    __syncthreads();
    if (tid == 0) {
        float fs = 0.f; unsigned ue = 0;
#pragma unroll
        for (int w = 0; w < 8; w++) { fs += warp_f[w]; ue += warp_u[w]; }
        s_sum = fs; s_eq = ue;
    }
    __syncthreads();

    const float eth   = __expf(thrf - m);
    const float denom = s_sum + (float)r * eth;
    const float inv   = 1.0f / denom;
    const float peq   = eth * inv;
    const bool  fast  = (s_eq == r);       // uniform across block

    if (fast) {
        if (tid == 0) g_rp[blockIdx.x] = make_float4(thrf, m, inv, peq);
    } else {
        // rare exact-tie path: materialize probs into S, sentinel param
        for (int i = tid; i < LSEQ; i += 256) {
            unsigned key = keys[i];
            srow[i] = (key > thr_key) ? __expf(key2f(key) - m) * inv : 0.f;
        }
        __syncthreads();
        if (tid == 0) {
            unsigned cnt = 0;
            for (int i = 0; i < LSEQ; i++) {
                if (keys[i] == thr_key) {
                    if (cnt < r) srow[i] = peq;
                    cnt++;
                }
            }
            g_rp[blockIdx.x] = make_float4(0.f, 0.f, -1.f, 0.f);
        }
    }
}

// ============================================================
// attnv (wmma, inline softmax + fp16x3): ctx = softmax(S) @ V per (b,h)
// Reads raw scores + per-row params; computes p inline (identical values
// to the materialized version), scales x1024, splits, 3-term HMMA.
// ============================================================
__global__ __launch_bounds__(256) void attnv_wmma_kernel()
{
    __shared__ __align__(16) __half Ph[128][40], Pl[128][40];
    __shared__ __align__(16) __half Vh[32][72], Vl[32][72];
    const int tid = threadIdx.x;
    const int wid = tid >> 5;
    const int wr = wid >> 1;           // 0..3 -> rows wr*32
    const int wc = wid & 1;            // 0..1 -> cols wc*32
    const int bh = blockIdx.z, b = bh >> 4, h = bh & 15;
    const int m0 = blockIdx.x * 128;

    const float* Pb = g_S + (size_t)bh * LSEQ * LSEQ + (size_t)m0 * LSEQ;
    const float4* Rp = g_rp + (size_t)bh * LSEQ + m0;
    const float* Vb = g_V + (size_t)b * LSEQ * DMODEL + h * DKH;

    wmma::fragment<wmma::accumulator, 16, 16, 16, float> acc[2][2];
#pragma unroll
    for (int i = 0; i < 2; i++)
#pragma unroll
        for (int j = 0; j < 2; j++)
            wmma::fill_fragment(acc[i][j], 0.0f);

    for (int k0 = 0; k0 < LSEQ; k0 += 32) {
#pragma unroll
        for (int it = 0; it < 4; it++) {
            int f = tid + 256 * it;
            int r = f >> 3, c4 = (f & 7) * 4;
            float4 rp = Rp[r];
            float4 pv = *(const float4*)(Pb + (size_t)r * LSEQ + k0 + c4);
            float sa[4] = {pv.x, pv.y, pv.z, pv.w};
            float pa[4];
#pragma unroll
            for (int e = 0; e < 4; e++) {
                float s = sa[e];
                float p;
                if (rp.z < 0.f)       p = s;                       // pre-materialized
                else if (s > rp.x)    p = __expf(s - rp.y) * rp.z; // top-k member
                else if (s == rp.x)   p = rp.w;                    // threshold (fast)
                else                  p = 0.f;
                pa[e] = p * PSCALE;
            }
#pragma unroll
            for (int e = 0; e < 4; e++) {
                __half ph = __float2half(pa[e]);
                Ph[r][c4 + e] = ph;
                Pl[r][c4 + e] = __float2half(pa[e] - __half2float(ph));
            }
        }
#pragma unroll
        for (int it = 0; it < 2; it++) {
            int f = tid + 256 * it;
            int r = f >> 4, c4 = (f & 15) * 4;
            float4 vv = *(const float4*)(Vb + (size_t)(k0 + r) * DMODEL + c4);
            float va[4] = {vv.x, vv.y, vv.z, vv.w};
#pragma unroll
            for (int e = 0; e < 4; e++) {
                __half vh = __float2half(va[e]);
                Vh[r][c4 + e] = vh;
                Vl[r][c4 + e] = __float2half(va[e] - __half2float(vh));
            }
        }
        __syncthreads();
#pragma unroll
        for (int kk = 0; kk < 32; kk += 16) {
            wmma::fragment<wmma::matrix_b, 16, 16, 16, __half, wmma::row_major> bh_f[2], bl_f[2];
#pragma unroll
            for (int j = 0; j < 2; j++) {
                wmma::load_matrix_sync(bh_f[j], &Vh[kk][wc * 32 + j * 16], 72);
                wmma::load_matrix_sync(bl_f[j], &Vl[kk][wc * 32 + j * 16], 72);
            }
#pragma unroll
            for (int i = 0; i < 2; i++) {
                wmma::fragment<wmma::matrix_a, 16, 16, 16, __half, wmma::row_major> ah_f, al_f;
                wmma::load_matrix_sync(ah_f, &Ph[wr * 32 + i * 16][kk], 40);
                wmma::load_matrix_sync(al_f, &Pl[wr * 32 + i * 16][kk], 40);
#pragma unroll
                for (int j = 0; j < 2; j++) {
                    wmma::mma_sync(acc[i][j], ah_f, bh_f[j], acc[i][j]);
                    wmma::mma_sync(acc[i][j], ah_f, bl_f[j], acc[i][j]);
                    wmma::mma_sync(acc[i][j], al_f, bh_f[j], acc[i][j]);
                }
            }
        }
        __syncthreads();
    }
    float* Cb = g_ctx + (size_t)(b * LSEQ + m0) * DMODEL + h * DKH;
    const float inv = 1.0f / PSCALE;
#pragma unroll
    for (int i = 0; i < 2; i++)
#pragma unroll
        for (int j = 0; j < 2; j++) {
#pragma unroll
            for (int e = 0; e < acc[i][j].num_elements; e++)
                acc[i][j].x[e] *= inv;
            wmma::store_matrix_sync(
                Cb + (size_t)(wr * 32 + i * 16) * DMODEL + wc * 32 + j * 16,
                acc[i][j], DMODEL, wmma::mem_row_major);
        }
}

// ============================================================
extern "C" void kernel_launch(void* const* d_in, const int* in_sizes, int n_in,
                              void* d_out, int out_size)
{
    const float* q  = (const float*)d_in[0];
    const float* k  = (const float*)d_in[1];
    const float* v  = (const float*)d_in[2];
    const float* Wq = (const float*)d_in[3];
    const float* bq = (const float*)d_in[4];
    const float* Wk = (const float*)d_in[5];
    const float* bk = (const float*)d_in[6];
    const float* Wv = (const float*)d_in[7];
    const float* bv = (const float*)d_in[8];
    const float* Wo = (const float*)d_in[9];
    const float* bo = (const float*)d_in[10];
    float* out = (float*)d_out;

    static float *gQ = nullptr, *gK = nullptr, *gV = nullptr, *gC = nullptr;
    static __half *gA = nullptr, *gB = nullptr;
    if (!gQ) {
        cudaGetSymbolAddress((void**)&gQ, g_Q);
        cudaGetSymbolAddress((void**)&gK, g_K);
        cudaGetSymbolAddress((void**)&gV, g_V);
        cudaGetSymbolAddress((void**)&gC, g_ctx);
        cudaGetSymbolAddress((void**)&gA, g_Asp);
        cudaGetSymbolAddress((void**)&gB, g_Bsp);
    }

    dim3 blk(256);
    const int NX = BLM * DMODEL;
    const int NW = DMODEL * DMODEL;
    dim3 gsx((NX + 255) / 256), gsw((NW + 255) / 256);
    dim3 gmm(DMODEL / 128, BLM / 128);  // (8, 32)

    // Q projection
    split_x_kernel<<<gsx, blk>>>(q, gA, NX);
    split_w_kernel<<<gsw, blk>>>(Wq, gB, NW);
    mm_wmma_kernel<<<gmm, blk>>>(gA, gB, bq, gQ);
    // K projection
    split_x_kernel<<<gsx, blk>>>(k, gA, NX);
    split_w_kernel<<<gsw, blk>>>(Wk, gB, NW);
    mm_wmma_kernel<<<gmm, blk>>>(gA, gB, bk, gK);
    // V projection
    split_x_kernel<<<gsx, blk>>>(v, gA, NX);
    split_w_kernel<<<gsw, blk>>>(Wv, gB, NW);
    mm_wmma_kernel<<<gmm, blk>>>(gA, gB, bv, gV);

    dim3 gsc(LSEQ / 128, LSEQ / 128, BHN);        // (16, 16, 32)
    scores_wmma_kernel<<<gsc, blk>>>();

    topk_softmax_kernel<<<BHN * LSEQ, blk>>>();   // 65536 blocks

    dim3 gav(LSEQ / 128, 1, BHN);                 // (16, 1, 32)
    attnv_wmma_kernel<<<gav, blk>>>();

    // Output projection
    split_x_kernel<<<gsx, blk>>>(gC, gA, NX);
    split_w_kernel<<<gsw, blk>>>(Wo, gB, NW);
    mm_wmma_kernel<<<gmm, blk>>>(gA, gB, bo, out);
}

// round 15
// speedup vs baseline: 1.9067x; 1.0309x over previous
#include <cuda_runtime.h>
#include <cuda_fp16.h>
#include <mma.h>

using namespace nvcuda;

#define BATCH   2
#define LSEQ    2048
#define DMODEL  1024
#define NHEADS  16
#define DKH     64
#define BHN     (BATCH * NHEADS)     // 32
#define BLM     (BATCH * LSEQ)       // 4096
#define TOPK    (LSEQ / 2)           // 1024
#define KSPLIT  3072                 // fp16x3 K-concat length
#define WSCALE  64.0f                // weight pre-scale
#define PSCALE  1024.0f              // prob pre-scale in attnv

// ---- scratch (static device arrays; allocation-free per harness rules) ----
__device__ float g_Q[(size_t)BLM * DMODEL];
__device__ float g_K[(size_t)BLM * DMODEL];
__device__ float g_V[(size_t)BLM * DMODEL];
__device__ float g_ctx[(size_t)BLM * DMODEL];
__device__ float g_S[(size_t)BHN * LSEQ * LSEQ];   // 537 MB scores
__device__ float4 g_rp[(size_t)BHN * LSEQ];        // per-row softmax params
__device__ __half g_A0[(size_t)BLM * KSPLIT];      // split activations (q / ctx)
__device__ __half g_A1[(size_t)BLM * KSPLIT];      // split activations (k)
__device__ __half g_A2[(size_t)BLM * KSPLIT];      // split activations (v)
__device__ __half g_B0[(size_t)DMODEL * KSPLIT];   // split Wq
__device__ __half g_B1[(size_t)DMODEL * KSPLIT];   // split Wk
__device__ __half g_B2[(size_t)DMODEL * KSPLIT];   // split Wv
__device__ __half g_B3[(size_t)DMODEL * KSPLIT];   // split Wo
__device__ float g_brep[4 * 16 * DMODEL];          // replicated bias tiles

// monotone float<->uint mapping (order-preserving)
__device__ __forceinline__ unsigned f2key(float f) {
    unsigned u = __float_as_uint(f);
    return (u & 0x80000000u) ? ~u : (u | 0x80000000u);
}
__device__ __forceinline__ float key2f(unsigned key) {
    unsigned u = (key & 0x80000000u) ? (key ^ 0x80000000u) : ~key;
    return __uint_as_float(u);
}

__device__ __forceinline__ void cp_async16(void* sptr, const void* gptr) {
    unsigned sa = (unsigned)__cvta_generic_to_shared(sptr);
    asm volatile("cp.async.cg.shared.global [%0], [%1], 16;" :: "r"(sa), "l"(gptr));
}
__device__ __forceinline__ void cp_commit() {
    asm volatile("cp.async.commit_group;" ::: "memory");
}
__device__ __forceinline__ void cp_wait1() {
    asm volatile("cp.async.wait_group 1;" ::: "memory");
}
__device__ __forceinline__ void cp_wait0() {
    asm volatile("cp.async.wait_group 0;" ::: "memory");
}

// ============================================================
// fp16x3 splits. X row -> [ah|ah|al]; W row (xWSCALE) -> [bh|bl|bh]
// ============================================================
__device__ __forceinline__ void split_x_body(
    const float* __restrict__ X, __half* __restrict__ O)
{
    int i = blockIdx.x * 256 + threadIdx.x;
    int r = i >> 10, c = i & 1023;
    float a = X[i];
    __half ah = __float2half(a);
    __half al = __float2half(a - __half2float(ah));
    __half* o = O + (size_t)r * KSPLIT;
    o[c] = ah; o[1024 + c] = ah; o[2048 + c] = al;
}
__global__ __launch_bounds__(256) void split_x3_kernel(
    const float* x0, const float* x1, const float* x2)
{
    const float* X = (blockIdx.z == 0) ? x0 : (blockIdx.z == 1) ? x1 : x2;
    __half* O = (blockIdx.z == 0) ? g_A0 : (blockIdx.z == 1) ? g_A1 : g_A2;
    split_x_body(X, O);
}
__global__ __launch_bounds__(256) void split_x1_kernel(const float* x0)
{
    split_x_body(x0, g_A0);
}
__global__ __launch_bounds__(256) void split_w4_kernel(
    const float* w0, const float* w1, const float* w2, const float* w3)
{
    const float* W = (blockIdx.z == 0) ? w0 : (blockIdx.z == 1) ? w1
                   : (blockIdx.z == 2) ? w2 : w3;
    __half* O = (blockIdx.z == 0) ? g_B0 : (blockIdx.z == 1) ? g_B1
              : (blockIdx.z == 2) ? g_B2 : g_B3;
    int i = blockIdx.x * 256 + threadIdx.x;
    int r = i >> 10, c = i & 1023;
    float b = W[i] * WSCALE;
    __half bh = __float2half(b);
    __half bl = __float2half(b - __half2float(bh));
    __half* o = O + (size_t)r * KSPLIT;
    o[c] = bh; o[1024 + c] = bl; o[2048 + c] = bh;
}
__global__ __launch_bounds__(256) void biasrep_kernel(
    const float* b0, const float* b1, const float* b2, const float* b3)
{
    const float* B = (blockIdx.z == 0) ? b0 : (blockIdx.z == 1) ? b1
                   : (blockIdx.z == 2) ? b2 : b3;
    int i = blockIdx.x * 256 + threadIdx.x;   // 0..16383
    g_brep[blockIdx.z * 16 * DMODEL + i] = B[i & 1023];
}

// ============================================================
// WMMA projection GEMM: Y = (X @ (WSCALE*W)^T)/WSCALE + bias
// CTA 128x128, 8 warps (2x4), warp 64x32. BK=32, cp.async 2-deep
// double buffer. Bias fragment loaded from replicated global tile.
// Per-acc mma chain: same ascending K=16 sequence (bit-identical).
// ============================================================
#define MST 40
__device__ __forceinline__ void mm_body(
    const __half* __restrict__ A, const __half* __restrict__ Bm,
    const float* __restrict__ brep, float* __restrict__ Y)
{
    __shared__ __align__(16) __half As[2][128][MST];   // 20480 B
    __shared__ __align__(16) __half Bs[2][128][MST];   // 20480 B

    const int tid = threadIdx.x;
    const int wid = tid >> 5;
    const int wr = wid >> 2;           // 0..1 -> rows wr*64
    const int wc = wid & 3;            // 0..3 -> cols wc*32
    const int m0 = blockIdx.y * 128, n0 = blockIdx.x * 128;

    const int lr = tid >> 1;           // 0..127
    const int lu = (tid & 1) * 16;     // 0 or 16 halves (32 B)
    const __half* Ab = A + (size_t)(m0 + lr) * KSPLIT + lu;
    const __half* Bb = Bm + (size_t)(n0 + lr) * KSPLIT + lu;

    const int NST = KSPLIT / 32;       // 96 stages

    // prologue: stages 0 and 1 in flight
#pragma unroll
    for (int s = 0; s < 2; s++) {
        cp_async16(&As[s][lr][lu], Ab + s * 32);
        cp_async16(&As[s][lr][lu + 8], Ab + s * 32 + 8);
        cp_async16(&Bs[s][lr][lu], Bb + s * 32);
        cp_async16(&Bs[s][lr][lu + 8], Bb + s * 32 + 8);
        cp_commit();
    }

    wmma::fragment<wmma::accumulator, 16, 16, 16, float> acc[4][2];
#pragma unroll
    for (int i = 0; i < 4; i++)
#pragma unroll
        for (int j = 0; j < 2; j++)
            wmma::fill_fragment(acc[i][j], 0.0f);

    for (int s = 0; s < NST; s++) {
        if (s + 1 < NST) cp_wait1(); else cp_wait0();
        __syncthreads();
        const int buf = s & 1;
#pragma unroll
        for (int kk = 0; kk < 32; kk += 16) {
            wmma::fragment<wmma::matrix_b, 16, 16, 16, __half, wmma::col_major> bf[2];
#pragma unroll
            for (int j = 0; j < 2; j++)
                wmma::load_matrix_sync(bf[j], &Bs[buf][wc * 32 + j * 16][kk], MST);
#pragma unroll
            for (int i = 0; i < 4; i++) {
                wmma::fragment<wmma::matrix_a, 16, 16, 16, __half, wmma::row_major> af;
                wmma::load_matrix_sync(af, &As[buf][wr * 64 + i * 16][kk], MST);
#pragma unroll
                for (int j = 0; j < 2; j++)
                    wmma::mma_sync(acc[i][j], af, bf[j], acc[i][j]);
            }
        }
        __syncthreads();
        if (s + 2 < NST) {
            const int nb = buf;        // (s+2)&1 == s&1
            int ko = (s + 2) * 32;
            cp_async16(&As[nb][lr][lu], Ab + ko);
            cp_async16(&As[nb][lr][lu + 8], Ab + ko + 8);
            cp_async16(&Bs[nb][lr][lu], Bb + ko);
            cp_async16(&Bs[nb][lr][lu + 8], Bb + ko + 8);
            cp_commit();
        }
    }

    const float inv = 1.0f / WSCALE;
#pragma unroll
    for (int i = 0; i < 4; i++)
#pragma unroll
        for (int j = 0; j < 2; j++) {
            wmma::fragment<wmma::accumulator, 16, 16, 16, float> bfr;
            wmma::load_matrix_sync(bfr, brep + n0 + wc * 32 + j * 16, DMODEL,
                                   wmma::mem_row_major);
#pragma unroll
            for (int e = 0; e < acc[i][j].num_elements; e++)
                acc[i][j].x[e] = acc[i][j].x[e] * inv + bfr.x[e];
            wmma::store_matrix_sync(
                Y + (size_t)(m0 + wr * 64 + i * 16) * DMODEL + n0 + wc * 32 + j * 16,
                acc[i][j], DMODEL, wmma::mem_row_major);
        }
}
__global__ __launch_bounds__(256) void mm_qkv_kernel()
{
    if (blockIdx.z == 0)      mm_body(g_A0, g_B0, g_brep + 0 * 16 * DMODEL, g_Q);
    else if (blockIdx.z == 1) mm_body(g_A1, g_B1, g_brep + 1 * 16 * DMODEL, g_K);
    else                      mm_body(g_A2, g_B2, g_brep + 2 * 16 * DMODEL, g_V);
}
__global__ __launch_bounds__(256) void mm_out_kernel(float* __restrict__ Y)
{
    mm_body(g_A0, g_B3, g_brep + 3 * 16 * DMODEL, Y);
}

// ============================================================
// Scores (wmma, inline fp16x3): S[bh][q][k] = (Q . K) / 8  (unchanged)
// ============================================================
__global__ __launch_bounds__(256) void scores_wmma_kernel()
{
    __shared__ __align__(16) __half Qh[128][40], Ql[128][40];
    __shared__ __align__(16) __half Kh[128][40], Kl[128][40];
    const int tid = threadIdx.x;
    const int wid = tid >> 5;
    const int wr = wid >> 2;
    const int wc = wid & 3;
    const int bh = blockIdx.z, b = bh >> 4, h = bh & 15;
    const int q0 = blockIdx.y * 128, k0 = blockIdx.x * 128;
    const float* Qb = g_Q + (size_t)(b * LSEQ + q0) * DMODEL + h * DKH;
    const float* Kb = g_K + (size_t)(b * LSEQ + k0) * DMODEL + h * DKH;

    wmma::fragment<wmma::accumulator, 16, 16, 16, float> acc[4][2];
#pragma unroll
    for (int i = 0; i < 4; i++)
#pragma unroll
        for (int j = 0; j < 2; j++)
            wmma::fill_fragment(acc[i][j], 0.0f);

    for (int kc = 0; kc < DKH; kc += 32) {
#pragma unroll
        for (int it = 0; it < 4; it++) {
            int f = tid + 256 * it;
            int r = f >> 3, c4 = (f & 7) * 4;
            float4 qv = *(const float4*)(Qb + (size_t)r * DMODEL + kc + c4);
            float4 kv = *(const float4*)(Kb + (size_t)r * DMODEL + kc + c4);
            float qa[4] = {qv.x, qv.y, qv.z, qv.w};
            float ka[4] = {kv.x, kv.y, kv.z, kv.w};
#pragma unroll
            for (int e = 0; e < 4; e++) {
                __half qh = __float2half(qa[e]);
                Qh[r][c4 + e] = qh;
                Ql[r][c4 + e] = __float2half(qa[e] - __half2float(qh));
                __half kh = __float2half(ka[e]);
                Kh[r][c4 + e] = kh;
                Kl[r][c4 + e] = __float2half(ka[e] - __half2float(kh));
            }
        }
        __syncthreads();
#pragma unroll
        for (int kk = 0; kk < 32; kk += 16) {
            wmma::fragment<wmma::matrix_b, 16, 16, 16, __half, wmma::col_major> bh_f[2], bl_f[2];
#pragma unroll
            for (int j = 0; j < 2; j++) {
                wmma::load_matrix_sync(bh_f[j], &Kh[wc * 32 + j * 16][kk], 40);
                wmma::load_matrix_sync(bl_f[j], &Kl[wc * 32 + j * 16][kk], 40);
            }
#pragma unroll
            for (int i = 0; i < 4; i++) {
                wmma::fragment<wmma::matrix_a, 16, 16, 16, __half, wmma::row_major> ah_f, al_f;
                wmma::load_matrix_sync(ah_f, &Qh[wr * 64 + i * 16][kk], 40);
                wmma::load_matrix_sync(al_f, &Ql[wr * 64 + i * 16][kk], 40);
#pragma unroll
                for (int j = 0; j < 2; j++) {
                    wmma::mma_sync(acc[i][j], ah_f, bh_f[j], acc[i][j]);
                    wmma::mma_sync(acc[i][j], ah_f, bl_f[j], acc[i][j]);
                    wmma::mma_sync(acc[i][j], al_f, bh_f[j], acc[i][j]);
                }
            }
        }
        __syncthreads();
    }
    float* Sb = g_S + (size_t)bh * LSEQ * LSEQ;
#pragma unroll
    for (int i = 0; i < 4; i++)
#pragma unroll
        for (int j = 0; j < 2; j++) {
#pragma unroll
            for (int e = 0; e < acc[i][j].num_elements; e++)
                acc[i][j].x[e] *= 0.125f;
            wmma::store_matrix_sync(
                Sb + (size_t)(q0 + wr * 64 + i * 16) * LSEQ + k0 + wc * 32 + j * 16,
                acc[i][j], LSEQ, wmma::mem_row_major);
        }
}

// ============================================================
// Per-row top-k threshold + softmax params (unchanged)
// ============================================================
__global__ __launch_bounds__(256) void topk_softmax_kernel()
{
    __shared__ unsigned keys[LSEQ];
    __shared__ unsigned hist[256];
    __shared__ unsigned warp_u[8];
    __shared__ float    warp_f[8];
    __shared__ unsigned s_sel, s_kkn, s_max, s_eq;
    __shared__ float    s_sum;

    const int tid  = threadIdx.x;
    const int lane = tid & 31, wid = tid >> 5;
    float* __restrict__ srow = g_S + (size_t)blockIdx.x * LSEQ;

    unsigned lmax = 0;
    for (int i = tid; i < LSEQ; i += 256) {
        unsigned key = f2key(srow[i]);
        keys[i] = key;
        lmax = key > lmax ? key : lmax;
    }
#pragma unroll
    for (int off = 16; off > 0; off >>= 1) {
        unsigned o = __shfl_xor_sync(0xffffffffu, lmax, off);
        lmax = o > lmax ? o : lmax;
    }
    if (lane == 0) warp_u[wid] = lmax;
    __syncthreads();
    if (tid == 0) {
        unsigned m = warp_u[0];
#pragma unroll
        for (int w = 1; w < 8; w++) m = warp_u[w] > m ? warp_u[w] : m;
        s_max = m;
    }
    __syncthreads();
    const unsigned maxkey = s_max;

    unsigned prefix = 0;
    unsigned kneed  = TOPK;
    for (int shift = 24; shift >= 0; shift -= 8) {
        hist[tid] = 0;
        __syncthreads();
        unsigned mask_hi = (shift == 24) ? 0u : (0xFFFFFFFFu << (shift + 8));
        for (int i = tid; i < LSEQ; i += 256) {
            unsigned key = keys[i];
            if ((key & mask_hi) == prefix)
                atomicAdd(&hist[(key >> shift) & 0xFFu], 1u);
        }
        __syncthreads();
        const unsigned h = hist[tid];
        unsigned v = h;
#pragma unroll
        for (int off = 1; off < 32; off <<= 1) {
            unsigned t = __shfl_down_sync(0xffffffffu, v, off);
            if (lane + off < 32) v += t;
        }
        if (lane == 0) warp_u[wid] = v;
        __syncthreads();
        unsigned wtail = 0;
#pragma unroll
        for (int w = 0; w < 8; w++) if (w > wid) wtail += warp_u[w];
        const unsigned sufi = v + wtail;
        const unsigned sufn = sufi - h;
        if (sufi >= kneed && sufn < kneed) {
            s_sel = (unsigned)tid;
            s_kkn = kneed - sufn;
        }
        __syncthreads();
        prefix |= (s_sel << shift);
        kneed = s_kkn;
    }
    const unsigned thr_key = prefix;
    const unsigned r = kneed;
    const float m    = key2f(maxkey);
    const float thrf = key2f(thr_key);

    float lsum = 0.f; unsigned leq = 0;
    for (int i = tid; i < LSEQ; i += 256) {
        unsigned key = keys[i];
        if (key > thr_key)       lsum += __expf(key2f(key) - m);
        else if (key == thr_key) leq++;
    }
#pragma unroll
    for (int off = 16; off > 0; off >>= 1) {
        lsum += __shfl_xor_sync(0xffffffffu, lsum, off);
        leq  += __shfl_xor_sync(0xffffffffu, leq,  off);
    }
    if (lane == 0) { warp_f[wid] = lsum; warp_u[wid] = leq; }
    __syncthreads();
    if (tid == 0) {
        float fs = 0.f; unsigned ue = 0;
#pragma unroll
        for (int w = 0; w < 8; w++) { fs += warp_f[w]; ue += warp_u[w]; }
        s_sum = fs; s_eq = ue;
    }
    __syncthreads();

    const float eth   = __expf(thrf - m);
    const float denom = s_sum + (float)r * eth;
    const float inv   = 1.0f / denom;
    const float peq   = eth * inv;
    const bool  fast  = (s_eq == r);

    if (fast) {
        if (tid == 0) g_rp[blockIdx.x] = make_float4(thrf, m, inv, peq);
    } else {
        for (int i = tid; i < LSEQ; i += 256) {
            unsigned key = keys[i];
            srow[i] = (key > thr_key) ? __expf(key2f(key) - m) * inv : 0.f;
        }
        __syncthreads();
        if (tid == 0) {
            unsigned cnt = 0;
            for (int i = 0; i < LSEQ; i++) {
                if (keys[i] == thr_key) {
                    if (cnt < r) srow[i] = peq;
                    cnt++;
                }
            }
            g_rp[blockIdx.x] = make_float4(0.f, 0.f, -1.f, 0.f);
        }
    }
}

// ============================================================
// attnv (wmma, inline softmax + fp16x3) (unchanged)
// ============================================================
__global__ __launch_bounds__(256) void attnv_wmma_kernel()
{
    __shared__ __align__(16) __half Ph[128][40], Pl[128][40];
    __shared__ __align__(16) __half Vh[32][72], Vl[32][72];
    const int tid = threadIdx.x;
    const int wid = tid >> 5;
    const int wr = wid >> 1;
    const int wc = wid & 1;
    const int bh = blockIdx.z, b = bh >> 4, h = bh & 15;
    const int m0 = blockIdx.x * 128;

    const float* Pb = g_S + (size_t)bh * LSEQ * LSEQ + (size_t)m0 * LSEQ;
    const float4* Rp = g_rp + (size_t)bh * LSEQ + m0;
    const float* Vb = g_V + (size_t)b * LSEQ * DMODEL + h * DKH;

    wmma::fragment<wmma::accumulator, 16, 16, 16, float> acc[2][2];
#pragma unroll
    for (int i = 0; i < 2; i++)
#pragma unroll
        for (int j = 0; j < 2; j++)
            wmma::fill_fragment(acc[i][j], 0.0f);

    for (int k0 = 0; k0 < LSEQ; k0 += 32) {
#pragma unroll
        for (int it = 0; it < 4; it++) {
            int f = tid + 256 * it;
            int r = f >> 3, c4 = (f & 7) * 4;
            float4 rp = Rp[r];
            float4 pv = *(const float4*)(Pb + (size_t)r * LSEQ + k0 + c4);
            float sa[4] = {pv.x, pv.y, pv.z, pv.w};
            float pa[4];
#pragma unroll
            for (int e = 0; e < 4; e++) {
                float s = sa[e];
                float p;
                if (rp.z < 0.f)       p = s;
                else if (s > rp.x)    p = __expf(s - rp.y) * rp.z;
                else if (s == rp.x)   p = rp.w;
                else                  p = 0.f;
                pa[e] = p * PSCALE;
            }
#pragma unroll
            for (int e = 0; e < 4; e++) {
                __half ph = __float2half(pa[e]);
                Ph[r][c4 + e] = ph;
                Pl[r][c4 + e] = __float2half(pa[e] - __half2float(ph));
            }
        }
#pragma unroll
        for (int it = 0; it < 2; it++) {
            int f = tid + 256 * it;
            int r = f >> 4, c4 = (f & 15) * 4;
            float4 vv = *(const float4*)(Vb + (size_t)(k0 + r) * DMODEL + c4);
            float va[4] = {vv.x, vv.y, vv.z, vv.w};
#pragma unroll
            for (int e = 0; e < 4; e++) {
                __half vh = __float2half(va[e]);
                Vh[r][c4 + e] = vh;
                Vl[r][c4 + e] = __float2half(va[e] - __half2float(vh));
            }
        }
        __syncthreads();
#pragma unroll
        for (int kk = 0; kk < 32; kk += 16) {
            wmma::fragment<wmma::matrix_b, 16, 16, 16, __half, wmma::row_major> bh_f[2], bl_f[2];
#pragma unroll
            for (int j = 0; j < 2; j++) {
                wmma::load_matrix_sync(bh_f[j], &Vh[kk][wc * 32 + j * 16], 72);
                wmma::load_matrix_sync(bl_f[j], &Vl[kk][wc * 32 + j * 16], 72);
            }
#pragma unroll
            for (int i = 0; i < 2; i++) {
                wmma::fragment<wmma::matrix_a, 16, 16, 16, __half, wmma::row_major> ah_f, al_f;
                wmma::load_matrix_sync(ah_f, &Ph[wr * 32 + i * 16][kk], 40);
                wmma::load_matrix_sync(al_f, &Pl[wr * 32 + i * 16][kk], 40);
#pragma unroll
                for (int j = 0; j < 2; j++) {
                    wmma::mma_sync(acc[i][j], ah_f, bh_f[j], acc[i][j]);
                    wmma::mma_sync(acc[i][j], ah_f, bl_f[j], acc[i][j]);
                    wmma::mma_sync(acc[i][j], al_f, bh_f[j], acc[i][j]);
                }
            }
        }
        __syncthreads();
    }
    float* Cb = g_ctx + (size_t)(b * LSEQ + m0) * DMODEL + h * DKH;
    const float inv = 1.0f / PSCALE;
#pragma unroll
    for (int i = 0; i < 2; i++)
#pragma unroll
        for (int j = 0; j < 2; j++) {
#pragma unroll
            for (int e = 0; e < acc[i][j].num_elements; e++)
                acc[i][j].x[e] *= inv;
            wmma::store_matrix_sync(
                Cb + (size_t)(wr * 32 + i * 16) * DMODEL + wc * 32 + j * 16,
                acc[i][j], DMODEL, wmma::mem_row_major);
        }
}

// ============================================================
extern "C" void kernel_launch(void* const* d_in, const int* in_sizes, int n_in,
                              void* d_out, int out_size)
{
    const float* q  = (const float*)d_in[0];
    const float* k  = (const float*)d_in[1];
    const float* v  = (const float*)d_in[2];
    const float* Wq = (const float*)d_in[3];
    const float* bq = (const float*)d_in[4];
    const float* Wk = (const float*)d_in[5];
    const float* bk = (const float*)d_in[6];
    const float* Wv = (const float*)d_in[7];
    const float* bv = (const float*)d_in[8];
    const float* Wo = (const float*)d_in[9];
    const float* bo = (const float*)d_in[10];
    float* out = (float*)d_out;

    static float* gC = nullptr;
    if (!gC) cudaGetSymbolAddress((void**)&gC, g_ctx);

    dim3 blk(256);
    const int NX = BLM * DMODEL;
    const int NW = DMODEL * DMODEL;

    // weight splits + bias replication (all 4 projections upfront)
    dim3 gsw(NW / 256, 1, 4);
    split_w4_kernel<<<gsw, blk>>>(Wq, Wk, Wv, Wo);
    dim3 gbr(16 * DMODEL / 256, 1, 4);
    biasrep_kernel<<<gbr, blk>>>(bq, bk, bv, bo);

    // q/k/v activation splits (one launch)
    dim3 gsx(NX / 256, 1, 3);
    split_x3_kernel<<<gsx, blk>>>(q, k, v);

    // QKV projections (one launch)
    dim3 gmm(DMODEL / 128, BLM / 128, 3);   // (8, 32, 3)
    mm_qkv_kernel<<<gmm, blk>>>();

    dim3 gsc(LSEQ / 128, LSEQ / 128, BHN);  // (16, 16, 32)
    scores_wmma_kernel<<<gsc, blk>>>();

    topk_softmax_kernel<<<BHN * LSEQ, blk>>>();

    dim3 gav(LSEQ / 128, 1, BHN);           // (16, 1, 32)
    attnv_wmma_kernel<<<gav, blk>>>();

    // output projection
    dim3 gsx1(NX / 256);
    split_x1_kernel<<<gsx1, blk>>>(gC);
    dim3 gmo(DMODEL / 128, BLM / 128);
    mm_out_kernel<<<gmo, blk>>>(out);
}